// round 14
// baseline (speedup 1.0000x reference)
#include <cuda_runtime.h>
#include <cuda_fp16.h>
#include <math.h>

#define H 1024
#define H4 256        // H/4 (float4 count)
#define H8 128        // H/8 (uint4-of-half count)
#define L 256
#define V 32000
#define NB 148        // one block per SM
#define NG 128        // blocks that own LSTM gate units
#define NA 116        // logits blocks (0..115)
#define NT 1024

// ---------------- persistent device state ----------------
__device__ float g_xemb[L*H];
__device__ float g_E[L*H];
__device__ float g_ET[H*L];             // E transposed: [j][t] for coalesced ctx
__device__ float g_Ew2[L*H];
__device__ float g_pih[L*4*H];          // precomputed eWih @ x(t) for all t (4MB)
__device__ float g_hhpart[4*H];         // dWhh @ h (computed by B blocks in slack)
__device__ float g_h[2][H];
__device__ float g_w1h[H];
__device__ float g_scores[L];
__device__ float g_xin[2*H];            // [relu(prev_emb) | ctx]
__device__ unsigned long long g_part[NA];

// tree barriers (monotonic, never reset)
__device__ unsigned g_c1[10], g_c2;  __device__ volatile unsigned g_ep;
__device__ unsigned a_c1[8],  a_c2;  __device__ volatile unsigned a_ep;
__device__ unsigned b_c1[2],  b_c2;  __device__ volatile unsigned b_ep;

// fp16 weight copies (static, no allocs)
__device__ uint4 g_outW[(size_t)V*H/8];
__device__ uint4 g_dWih[(size_t)4*H*2*H/8];
__device__ uint4 g_dWhh[(size_t)4*H*H/8];
__device__ uint4 g_eWih[(size_t)4*H*H/8];
__device__ uint4 g_eWhh[(size_t)4*H*H/8];

// ---------------- prep: init (block 0) + fp32->fp16 conversion (graph node 1) ----
__device__ __forceinline__ void cvt_range(uint2* dst, const float4* src,
                                          size_t n, size_t t0, size_t stride) {
    for (size_t i = t0; i < n; i += stride) {
        float4 f = src[i];
        __half2 a = __floats2half2_rn(f.x, f.y), b = __floats2half2_rn(f.z, f.w);
        dst[i] = make_uint2(*(unsigned*)&a, *(unsigned*)&b);
    }
}

__global__ void prep_kernel(const float* __restrict__ outW,
                            const float* __restrict__ dWih,
                            const float* __restrict__ dWhh,
                            const float* __restrict__ eWih,
                            const float* __restrict__ eWhh)
{
    if (blockIdx.x == 0) {                       // init block
        int t = threadIdx.x;
        if (t < 10) g_c1[t] = 0;
        if (t < 8)  a_c1[t] = 0;
        if (t < 2)  b_c1[t] = 0;
        if (t == 0) { g_c2 = 0; a_c2 = 0; b_c2 = 0; g_ep = 0; a_ep = 0; b_ep = 0; }
        for (int k = t; k < H; k += blockDim.x) {
            g_h[0][k] = 0.f; g_h[1][k] = 0.f;
            g_xin[k] = 0.f;  g_xin[H + k] = 0.f;
        }
    }
    size_t stride = (size_t)gridDim.x * blockDim.x;
    size_t t0 = (size_t)blockIdx.x * blockDim.x + threadIdx.x;
    cvt_range((uint2*)g_outW, (const float4*)outW, (size_t)V*H/4,     t0, stride);
    cvt_range((uint2*)g_dWih, (const float4*)dWih, (size_t)4*H*2*H/4, t0, stride);
    cvt_range((uint2*)g_dWhh, (const float4*)dWhh, (size_t)4*H*H/4,   t0, stride);
    cvt_range((uint2*)g_eWih, (const float4*)eWih, (size_t)4*H*H/4,   t0, stride);
    cvt_range((uint2*)g_eWhh, (const float4*)eWhh, (size_t)4*H*H/4,   t0, stride);
}

// ---------------- tree grid barrier: 10 groups of <=16 -> root of 10 ----------------
__device__ __forceinline__ void gsync(unsigned t) {
    __syncthreads();
    if (threadIdx.x == 0) {
        __threadfence();
        unsigned grp = (unsigned)blockIdx.x >> 4;            // 0..9
        unsigned sz  = (grp == 9) ? 4u : 16u;                // 148 = 9*16 + 4
        if (atomicAdd(&g_c1[grp], 1u) + 1u == t * sz)
            if (atomicAdd(&g_c2, 1u) + 1u == t * 10u)
                g_ep = t;
        while (g_ep < t) { }
    }
    __syncthreads();
}

// A-barrier (blocks 0..115): arrive always, spin only if requested (block 0)
__device__ __forceinline__ void async_bar(unsigned t, bool spin) {
    __syncthreads();
    if (threadIdx.x == 0) {
        __threadfence();
        unsigned grp = (unsigned)blockIdx.x >> 4;            // 0..7
        unsigned sz  = (grp == 7) ? 4u : 16u;                // 116 = 7*16 + 4
        if (atomicAdd(&a_c1[grp], 1u) + 1u == t * sz)
            if (atomicAdd(&a_c2, 1u) + 1u == t * 8u)
                a_ep = t;
        if (spin) while (a_ep < t) { }
    }
    __syncthreads();
}

// B-barrier (blocks 116..147): all spin
__device__ __forceinline__ void bsync_bar(unsigned t) {
    __syncthreads();
    if (threadIdx.x == 0) {
        __threadfence();
        unsigned grp = ((unsigned)blockIdx.x - NA) >> 4;     // 0..1, 16 each
        if (atomicAdd(&b_c1[grp], 1u) + 1u == t * 16u)
            if (atomicAdd(&b_c2, 1u) + 1u == t * 2u)
                b_ep = t;
        while (b_ep < t) { }
    }
    __syncthreads();
}

__device__ __forceinline__ float warp_red(float v) {
    #pragma unroll
    for (int o = 16; o > 0; o >>= 1) v += __shfl_down_sync(0xffffffffu, v, o);
    return v;
}

// 2-way interleaved reduction: overlaps the SHFL latency chains
__device__ __forceinline__ void warp_red2(float& s0, float& s1) {
    #pragma unroll
    for (int o = 16; o > 0; o >>= 1) {
        s0 += __shfl_down_sync(0xffffffffu, s0, o);
        s1 += __shfl_down_sync(0xffffffffu, s1, o);
    }
}

__device__ __forceinline__ float dot4(const float4 w, const float4 a) {
    return fmaf(w.x, a.x, fmaf(w.y, a.y, fmaf(w.z, a.z, w.w * a.w)));
}

__device__ __forceinline__ float dot8h(uint4 q, const float4* __restrict__ s, int k) {
    float2 f0 = __half22float2(*(__half2*)&q.x);
    float2 f1 = __half22float2(*(__half2*)&q.y);
    float2 f2 = __half22float2(*(__half2*)&q.z);
    float2 f3 = __half22float2(*(__half2*)&q.w);
    float4 v0 = s[2*k], v1 = s[2*k+1];
    float r = fmaf(f0.x, v0.x, fmaf(f0.y, v0.y, fmaf(f1.x, v0.z, f1.y * v0.w)));
    return fmaf(f2.x, v1.x, fmaf(f2.y, v1.y, fmaf(f3.x, v1.z, fmaf(f3.y, v1.w, r))));
}

// register-activation variant: no smem reads in the hot loop
__device__ __forceinline__ float dot8h_reg(uint4 q, float4 v0, float4 v1) {
    float2 f0 = __half22float2(*(__half2*)&q.x);
    float2 f1 = __half22float2(*(__half2*)&q.y);
    float2 f2 = __half22float2(*(__half2*)&q.z);
    float2 f3 = __half22float2(*(__half2*)&q.w);
    float r = fmaf(f0.x, v0.x, fmaf(f0.y, v0.y, fmaf(f1.x, v0.z, f1.y * v0.w)));
    return fmaf(f2.x, v1.x, fmaf(f2.y, v1.y, fmaf(f3.x, v1.z, fmaf(f3.y, v1.w, r))));
}

__device__ __forceinline__ float row_dot(int r, int lane,
    float4 a0, float4 a1, float4 a2, float4 a3,
    float4 a4, float4 a5, float4 a6, float4 a7)
{
    const uint4* wr = g_outW + (size_t)r * H8;
    return dot8h_reg(wr[lane],      a0, a1)
         + dot8h_reg(wr[lane + 32], a2, a3)
         + dot8h_reg(wr[lane + 64], a4, a5)
         + dot8h_reg(wr[lane + 96], a6, a7);
}

// ---------------- the whole model (graph node 2) ----------------
__global__ void __launch_bounds__(NT, 1) model_kernel(
    const int*   __restrict__ seq,   const float* __restrict__ embeds,
    const float* __restrict__ ebih,  const float* __restrict__ ebhh,
    const float* __restrict__ dbih,  const float* __restrict__ dbhh,
    const float* __restrict__ outb,
    const float* __restrict__ v,     const float* __restrict__ w1,
    const float* __restrict__ w2,
    float* __restrict__ out, float* __restrict__ out_seq)
{
    const int b = blockIdx.x, tid = threadIdx.x;
    const int warp = tid >> 5, lane = tid & 31;
    const int gg_ = warp >> 3, uu_ = warp & 7;        // gate / unit ownership
    unsigned epg = 0, epa = 0, epb = 0;

    __shared__ float s_vec[2*H];
    __shared__ float s_h[H];
    __shared__ float s_sc[L];
    __shared__ float s_red[32];
    __shared__ float s_red2[32];
    __shared__ unsigned long long s_key[32];
    __shared__ float s_r2[NT];
    __shared__ float s_c[8];
    __shared__ int   s_idx;

    if (tid < 8) s_c[tid] = 0.f;

    // ---- embedding gather ----
    for (int t = b; t < L; t += NB) {
        int id = seq[t];
        const float* src = embeds + (size_t)id * H;
        for (int k = tid; k < H; k += NT) g_xemb[t*H + k] = src[k];
    }
    gsync(++epg);

    // ---- precompute eWih @ x(t) for all t (block-local rows; weights L1-hot) ----
    if (b < NG) {
        int j = b * 8 + uu_;
        int r = gg_ * H + j;
        const uint4* wi = g_eWih + (size_t)r * H8;
        float4* sx = (float4*)s_vec;
        for (int t = 0; t < L; t++) {
            const float4* xv = (const float4*)(g_xemb + t*H);
            for (int k = tid; k < H4; k += NT) sx[k] = xv[k];
            __syncthreads();
            float s = 0.f;
            #pragma unroll
            for (int k = lane; k < H8; k += 32) s += dot8h(wi[k], sx, k);
            s = warp_red(s);
            if (lane == 0) g_pih[t*4*H + r] = s;
            __syncthreads();
        }
    }
    // no gsync needed: each block consumes only its own g_pih rows

    // ---- encoder: 256 steps, 1 barrier each (Whh only; Wih part precomputed) ----
    for (int t = 0; t < L; t++) {
        if (b < NG) {
            const float4* hv = (const float4*)g_h[t & 1];
            float4* sh = (float4*)s_h;
            for (int k = tid; k < H4; k += NT) sh[k] = __ldcg(hv + k);
            __syncthreads();
            int j = b * 8 + uu_;
            int r = gg_ * H + j;
            const uint4* wh = g_eWhh + (size_t)r * H8;
            float s = 0.f;
            #pragma unroll
            for (int k = lane; k < H8; k += 32) s += dot8h(wh[k], sh, k);
            s = warp_red(s);
            if (lane == 0) s_red2[warp] = s + g_pih[t*4*H + r];
            __syncthreads();
            if (tid < 8) {
                int jj = b * 8 + tid;
                float gi = s_red2[tid]      + ebih[jj]       + ebhh[jj];
                float gf = s_red2[8 + tid]  + ebih[H + jj]   + ebhh[H + jj];
                float gG = s_red2[16 + tid] + ebih[2*H + jj] + ebhh[2*H + jj];
                float go = s_red2[24 + tid] + ebih[3*H + jj] + ebhh[3*H + jj];
                float i_ = 1.f / (1.f + expf(-gi));
                float f_ = 1.f / (1.f + expf(-gf));
                float o_ = 1.f / (1.f + expf(-go));
                float cn = f_ * s_c[tid] + i_ * tanhf(gG);
                float hn = o_ * tanhf(cn);
                s_c[tid] = cn;
                g_h[(t+1)&1][jj] = hn;
                g_E[t*H + jj] = hn;
                g_ET[jj*L + t] = hn;
            }
        }
        gsync(++epg);
    }

    // ---- Ew2 = E @ w2^T (one-time, blocks 0..127) ----
    if (b < NG) {
        for (int rr = 0; rr < 2; rr++) {
            int i = 2*b + rr;
            const float4* Er = (const float4*)(g_E + i*H);
            float4* sh = (float4*)s_h;
            for (int k = tid; k < H4; k += NT) sh[k] = Er[k];
            __syncthreads();
            for (int j = warp; j < H; j += 32) {
                const float4* wr = (const float4*)(w2 + (size_t)j * H);
                float s = 0.f;
                #pragma unroll 4
                for (int k = lane; k < H4; k += 32) s += dot4(wr[k], sh[k]);
                s = warp_red(s);
                if (lane == 0) g_Ew2[i*H + j] = s;
            }
            __syncthreads();
        }
    }
    gsync(++epg);

    // ---- prologue: w1h(h0) on b<NG + hhpart(h0) on b>=NA ----
    if (b < NG) {
        float4* sh = (float4*)s_h;
        const float4* hv = (const float4*)g_h[0];
        for (int k = tid; k < H4; k += NT) sh[k] = __ldcg(hv + k);
        __syncthreads();
        if (warp < 8) {
            int r = b * 8 + warp;
            const float4* wr = (const float4*)(w1 + (size_t)r * H);
            float s = 0.f;
            #pragma unroll 4
            for (int k = lane; k < H4; k += 32) s += dot4(wr[k], sh[k]);
            s = warp_red(s);
            if (lane == 0) g_w1h[r] = s;
        }
    }
    if (b >= NA) {
        float4* svv = (float4*)s_vec;
        const float4* hv = (const float4*)g_h[0];
        for (int k = tid; k < H4; k += NT) svv[k] = __ldcg(hv + k);
        __syncthreads();
        int wq = (b - NA) * 32 + warp;               // 0..1023
        #pragma unroll
        for (int rr = 0; rr < 4; rr += 2) {
            int r0 = wq * 4 + rr, r1 = r0 + 1;
            const uint4* wh0 = g_dWhh + (size_t)r0 * H8;
            const uint4* wh1 = g_dWhh + (size_t)r1 * H8;
            float s0 = 0.f, s1 = 0.f;
            #pragma unroll 4
            for (int k = lane; k < H8; k += 32) {
                s0 += dot8h(wh0[k], svv, k);
                s1 += dot8h(wh1[k], svv, k);
            }
            warp_red2(s0, s1);
            if (lane == 0) { g_hhpart[r0] = s0; g_hhpart[r1] = s1; }
        }
    }
    gsync(++epg);
    if (b < NG) {   // scores(0): rows 2b, 2b+1
        float4* sh = (float4*)s_h;
        const float4* wv = (const float4*)g_w1h;
        for (int k = tid; k < H4; k += NT) sh[k] = __ldcg(wv + k);
        __syncthreads();
        for (int rr = 0; rr < 2; rr++) {
            int i = 2*b + rr;
            float val = v[tid] * tanhf(s_h[tid] + __ldcg(&g_Ew2[i*H + tid]));
            val = warp_red(val);
            if (lane == 0) s_red[warp] = val;
            __syncthreads();
            if (warp == 0) {
                float x = warp_red(s_red[lane]);
                if (lane == 0) g_scores[i] = x;
            }
            __syncthreads();
        }
    }
    gsync(++epg);
    if (b < NG) {   // softmax + ctx(0): 8 elements per block
        if (tid < L) s_sc[tid] = __ldcg(g_scores + tid);
        __syncthreads();
        float mval = (tid < L) ? s_sc[tid] : -3.0e38f;
        #pragma unroll
        for (int o = 16; o > 0; o >>= 1)
            mval = fmaxf(mval, __shfl_down_sync(0xffffffffu, mval, o));
        if (lane == 0) s_red[warp] = mval;
        __syncthreads();
        if (tid == 0) {
            float mm = s_red[0];
            for (int w_ = 1; w_ < 32; w_++) mm = fmaxf(mm, s_red[w_]);
            s_red[0] = mm;
        }
        __syncthreads();
        float mx = s_red[0];
        float evv = (tid < L) ? expf(s_sc[tid] - mx) : 0.f;
        __syncthreads();
        if (tid < L) s_sc[tid] = evv;
        float sv2 = warp_red(evv);
        if (lane == 0) s_red[warp] = sv2;
        __syncthreads();
        if (tid == 0) {
            float ss = 0.f;
            for (int w_ = 0; w_ < 32; w_++) ss += s_red[w_];
            s_red[0] = 1.f / ss;
        }
        __syncthreads();
        float inv = s_red[0];
        int q = tid >> 7, ii = tid & 127;
        int j = b * 8 + q;
        float acc = s_sc[ii]       * g_ET[j*L + ii]
                  + s_sc[ii + 128] * g_ET[j*L + ii + 128];
        s_r2[tid] = acc;
        __syncthreads();
        for (int st = 64; st > 0; st >>= 1) {
            if (ii < st) s_r2[tid] += s_r2[tid + st];
            __syncthreads();
        }
        if (ii == 0) g_xin[H + j] = s_r2[tid] * inv;
    }
    gsync(++epg);

    // ---- decoder: 256 steps, 2 global barriers each ----
    for (int d = 0; d < L; d++) {
        const int pout = (d + 1) & 1;

        // gates: blocks 0..127 — Wih@xin only; Whh@h precomputed by B blocks
        if (b < NG) {
            float4* sv = (float4*)s_vec;
            const float4* xv = (const float4*)g_xin;
            for (int k = tid; k < 2*H4; k += NT) sv[k] = __ldcg(xv + k);
            __syncthreads();
            int j = b * 8 + uu_;
            int r = gg_ * H + j;
            const uint4* wi = g_dWih + (size_t)r * (2*H8);
            float s = 0.f;
            #pragma unroll 4
            for (int k = lane; k < 2*H8; k += 32) s += dot8h(wi[k], sv, k);
            s = warp_red(s);
            if (lane == 0) s_red2[warp] = s + __ldcg(&g_hhpart[r]);
            __syncthreads();
            if (tid < 8) {
                int jj = b * 8 + tid;
                float gi = s_red2[tid]      + dbih[jj]       + dbhh[jj];
                float gf = s_red2[8 + tid]  + dbih[H + jj]   + dbhh[H + jj];
                float gG = s_red2[16 + tid] + dbih[2*H + jj] + dbhh[2*H + jj];
                float go = s_red2[24 + tid] + dbih[3*H + jj] + dbhh[3*H + jj];
                float i_ = 1.f / (1.f + expf(-gi));
                float f_ = 1.f / (1.f + expf(-gf));
                float o_ = 1.f / (1.f + expf(-go));
                float cn = f_ * s_c[tid] + i_ * tanhf(gG);
                float hn = o_ * tanhf(cn);
                s_c[tid] = cn;
                g_h[pout][jj] = hn;
            }
        }
        gsync(++epg);

        if (b < NA) {
            // ---- A: logits(d) + argmax + feedback (2-row ILP) ----
            float4* sh = (float4*)s_h;
            const float4* hv = (const float4*)g_h[pout];
            for (int k = tid; k < H4; k += NT) sh[k] = __ldcg(hv + k);
            __syncthreads();
            float4 a0 = sh[2*lane],            a1 = sh[2*lane + 1];
            float4 a2 = sh[2*(lane+32)],       a3 = sh[2*(lane+32) + 1];
            float4 a4 = sh[2*(lane+64)],       a5 = sh[2*(lane+64) + 1];
            float4 a6 = sh[2*(lane+96)],       a7 = sh[2*(lane+96) + 1];
            float bestv = -3.0e38f; int bestr = 0;
            float* od = out + (size_t)d * V;
            const int base = b * 32 + warp;
            for (int r = base; r < V; r += NA * 64) {
                int r2 = r + NA * 32;
                bool ok2 = (r2 < V);
                float s0 = row_dot(r, lane, a0,a1,a2,a3,a4,a5,a6,a7);
                float s1 = ok2 ? row_dot(r2, lane, a0,a1,a2,a3,a4,a5,a6,a7) : 0.f;
                warp_red2(s0, s1);
                if (lane == 0) {
                    s0 += outb[r];
                    __stcs(od + r, s0);
                    if (s0 > bestv) { bestv = s0; bestr = r; }
                    if (ok2) {
                        s1 += outb[r2];
                        __stcs(od + r2, s1);
                        if (s1 > bestv) { bestv = s1; bestr = r2; }
                    }
                }
            }
            if (lane == 0) {
                unsigned u = __float_as_uint(bestv);
                u = (u & 0x80000000u) ? ~u : (u | 0x80000000u);
                s_key[warp] = ((unsigned long long)u << 32) |
                              (unsigned long long)(0xFFFFFFFFu - (unsigned)bestr);
            }
            __syncthreads();
            if (tid == 0) {
                unsigned long long kk = s_key[0];
                for (int w_ = 1; w_ < 32; w_++) if (s_key[w_] > kk) kk = s_key[w_];
                g_part[b] = kk;
            }
            ++epa;
            async_bar(epa, b == 0);
            if (b == 0) {
                if (warp == 0) {
                    unsigned long long kk = 0ull;
                    for (int q = lane; q < NA; q += 32) {
                        unsigned long long t2 = __ldcg((const unsigned long long*)(g_part + q));
                        if (t2 > kk) kk = t2;
                    }
                    #pragma unroll
                    for (int o = 16; o > 0; o >>= 1) {
                        unsigned long long ok = __shfl_down_sync(0xffffffffu, kk, o);
                        if (ok > kk) kk = ok;
                    }
                    if (lane == 0)
                        s_idx = (int)(0xFFFFFFFFu - (unsigned)(kk & 0xFFFFFFFFull));
                }
                __syncthreads();
                int idx = s_idx;
                float e = embeds[(size_t)idx * H + tid];
                g_xin[tid] = fmaxf(e, 0.f);                  // feedback for step d+1
                if (tid == 0 && out_seq) out_seq[d] = (float)idx;
            }
        } else {
            // ---- B (116..147): w1h -> scores(d+1) -> softmax+ctx(d+1) -> hhpart ----
            const int q = b - NA;                            // 0..31
            float4* sh = (float4*)s_h;
            float4* svv = (float4*)s_vec;
            const float4* hv = (const float4*)g_h[pout];
            for (int k = tid; k < H4; k += NT) {
                float4 hx = __ldcg(hv + k);
                sh[k] = hx; svv[k] = hx;                     // keep h copy in s_vec
            }
            __syncthreads();
            {   // w1h: 32 rows per block, warp per row
                int r = q * 32 + warp;
                const float4* wr = (const float4*)(w1 + (size_t)r * H);
                float s = 0.f;
                #pragma unroll 4
                for (int k = lane; k < H4; k += 32) s += dot4(wr[k], sh[k]);
                s = warp_red(s);
                if (lane == 0) g_w1h[r] = s;
            }
            bsync_bar(++epb);
            for (int k = tid; k < H4; k += NT) sh[k] = __ldcg((const float4*)g_w1h + k);
            __syncthreads();
            for (int rr = 0; rr < 8; rr++) {                 // scores: 8 rows per block
                int i = q * 8 + rr;
                float val = v[tid] * tanhf(s_h[tid] + __ldcg(&g_Ew2[i*H + tid]));
                val = warp_red(val);
                if (lane == 0) s_red[warp] = val;
                __syncthreads();
                if (warp == 0) {
                    float x = warp_red(s_red[lane]);
                    if (lane == 0) g_scores[i] = x;
                }
                __syncthreads();
            }
            bsync_bar(++epb);
            {   // softmax (redundant) + ctx: 32 elements per block, warp per element
                if (tid < L) s_sc[tid] = __ldcg(g_scores + tid);
                __syncthreads();
                float mval = (tid < L) ? s_sc[tid] : -3.0e38f;
                #pragma unroll
                for (int o = 16; o > 0; o >>= 1)
                    mval = fmaxf(mval, __shfl_down_sync(0xffffffffu, mval, o));
                if (lane == 0) s_red[warp] = mval;
                __syncthreads();
                if (tid == 0) {
                    float mm = s_red[0];
                    for (int w_ = 1; w_ < 32; w_++) mm = fmaxf(mm, s_red[w_]);
                    s_red[0] = mm;
                }
                __syncthreads();
                float mx = s_red[0];
                float evv = (tid < L) ? expf(s_sc[tid] - mx) : 0.f;
                __syncthreads();
                if (tid < L) s_sc[tid] = evv;
                float sv2 = warp_red(evv);
                if (lane == 0) s_red[warp] = sv2;
                __syncthreads();
                if (tid == 0) {
                    float ss = 0.f;
                    for (int w_ = 0; w_ < 32; w_++) ss += s_red[w_];
                    s_red[0] = 1.f / ss;
                }
                __syncthreads();
                float inv = s_red[0];
                int j = q * 32 + warp;
                float acc = 0.f;
                #pragma unroll 4
                for (int i = lane; i < L; i += 32)
                    acc += s_sc[i] * __ldcg(&g_ET[j*L + i]);
                acc = warp_red(acc);
                if (lane == 0) g_xin[H + j] = acc * inv;
            }
            {   // hhpart for next step's gates: 4 rows per warp (h copy in s_vec)
                int wq = q * 32 + warp;                      // 0..1023
                #pragma unroll
                for (int rr = 0; rr < 4; rr += 2) {
                    int r0 = wq * 4 + rr, r1 = r0 + 1;
                    const uint4* wh0 = g_dWhh + (size_t)r0 * H8;
                    const uint4* wh1 = g_dWhh + (size_t)r1 * H8;
                    float s0 = 0.f, s1 = 0.f;
                    #pragma unroll 4
                    for (int k = lane; k < H8; k += 32) {
                        s0 += dot8h(wh0[k], svv, k);
                        s1 += dot8h(wh1[k], svv, k);
                    }
                    warp_red2(s0, s1);
                    if (lane == 0) { g_hhpart[r0] = s0; g_hhpart[r1] = s1; }
                }
            }
        }
        gsync(++epg);
    }
}

// ---------------- launch: 2-node graph ----------------
extern "C" void kernel_launch(void* const* d_in, const int* in_sizes, int n_in,
                              void* d_out, int out_size)
{
    const int*   seq    = (const int*)  d_in[0];
    const float* embeds = (const float*)d_in[1];
    const float* eWih = (const float*)d_in[2],  *eWhh = (const float*)d_in[3];
    const float* ebih = (const float*)d_in[4],  *ebhh = (const float*)d_in[5];
    const float* dWih = (const float*)d_in[6],  *dWhh = (const float*)d_in[7];
    const float* dbih = (const float*)d_in[8],  *dbhh = (const float*)d_in[9];
    const float* outW = (const float*)d_in[10], *outb = (const float*)d_in[11];
    const float* v    = (const float*)d_in[12];
    const float* w1   = (const float*)d_in[13], *w2   = (const float*)d_in[14];

    float* out = (float*)d_out;
    float* out_seq = (out_size >= L*V + L) ? out + (size_t)L*V : nullptr;

    prep_kernel<<<2048, 256>>>(outW, dWih, dWhh, eWih, eWhh);
    model_kernel<<<NB, NT>>>(seq, embeds, ebih, ebhh,
                             dbih, dbhh, outb, v, w1, w2, out, out_seq);
}

// round 15
// speedup vs baseline: 1.0026x; 1.0026x over previous
#include <cuda_runtime.h>
#include <cuda_fp16.h>
#include <math.h>

#define H 1024
#define H4 256        // H/4 (float4 count)
#define H8 128        // H/8 (uint4-of-half count)
#define L 256
#define V 32000
#define NB 148        // one block per SM
#define NG 128        // blocks that own LSTM gate units
#define NA 116        // logits blocks (0..115)
#define NT 1024

// ---------------- persistent device state ----------------
__device__ float g_xemb[L*H];
__device__ float g_E[L*H];
__device__ float g_ET[H*L];             // E transposed: [j][t] for coalesced ctx
__device__ float g_Ew2[L*H];
__device__ float g_pih[L*4*H];          // precomputed eWih @ x(t) for all t (4MB)
__device__ float g_hhpart[4*H];         // dWhh @ h (computed by B blocks in slack)
__device__ float g_h[2][H];
__device__ float g_w1h[H];
__device__ float g_scores[L];
__device__ float g_xin[2*H];            // [relu(prev_emb) | ctx]
__device__ unsigned long long g_part[NA];

// tree barriers (monotonic, never reset)
__device__ unsigned g_c1[10], g_c2;  __device__ volatile unsigned g_ep;
__device__ unsigned a_c1[8],  a_c2;  __device__ volatile unsigned a_ep;
__device__ unsigned b_c1[2],  b_c2;  __device__ volatile unsigned b_ep;

// fp16 weight copies (static, no allocs)
__device__ uint4 g_outW[(size_t)V*H/8];
__device__ uint4 g_dWih[(size_t)4*H*2*H/8];
__device__ uint4 g_dWhh[(size_t)4*H*H/8];
__device__ uint4 g_eWih[(size_t)4*H*H/8];
__device__ uint4 g_eWhh[(size_t)4*H*H/8];

// ---------------- prep: init (block 0) + fp32->fp16 conversion (graph node 1) ----
__device__ __forceinline__ void cvt_range(uint2* dst, const float4* src,
                                          size_t n, size_t t0, size_t stride) {
    for (size_t i = t0; i < n; i += stride) {
        float4 f = src[i];
        __half2 a = __floats2half2_rn(f.x, f.y), b = __floats2half2_rn(f.z, f.w);
        dst[i] = make_uint2(*(unsigned*)&a, *(unsigned*)&b);
    }
}

__global__ void prep_kernel(const float* __restrict__ outW,
                            const float* __restrict__ dWih,
                            const float* __restrict__ dWhh,
                            const float* __restrict__ eWih,
                            const float* __restrict__ eWhh)
{
    if (blockIdx.x == 0) {                       // init block
        int t = threadIdx.x;
        if (t < 10) g_c1[t] = 0;
        if (t < 8)  a_c1[t] = 0;
        if (t < 2)  b_c1[t] = 0;
        if (t == 0) { g_c2 = 0; a_c2 = 0; b_c2 = 0; g_ep = 0; a_ep = 0; b_ep = 0; }
        for (int k = t; k < H; k += blockDim.x) {
            g_h[0][k] = 0.f; g_h[1][k] = 0.f;
            g_xin[k] = 0.f;  g_xin[H + k] = 0.f;
        }
    }
    size_t stride = (size_t)gridDim.x * blockDim.x;
    size_t t0 = (size_t)blockIdx.x * blockDim.x + threadIdx.x;
    cvt_range((uint2*)g_outW, (const float4*)outW, (size_t)V*H/4,     t0, stride);
    cvt_range((uint2*)g_dWih, (const float4*)dWih, (size_t)4*H*2*H/4, t0, stride);
    cvt_range((uint2*)g_dWhh, (const float4*)dWhh, (size_t)4*H*H/4,   t0, stride);
    cvt_range((uint2*)g_eWih, (const float4*)eWih, (size_t)4*H*H/4,   t0, stride);
    cvt_range((uint2*)g_eWhh, (const float4*)eWhh, (size_t)4*H*H/4,   t0, stride);
}

// ---------------- tree grid barrier: 10 groups of <=16 -> root of 10 ----------------
__device__ __forceinline__ void gsync(unsigned t) {
    __syncthreads();
    if (threadIdx.x == 0) {
        __threadfence();
        unsigned grp = (unsigned)blockIdx.x >> 4;            // 0..9
        unsigned sz  = (grp == 9) ? 4u : 16u;                // 148 = 9*16 + 4
        if (atomicAdd(&g_c1[grp], 1u) + 1u == t * sz)
            if (atomicAdd(&g_c2, 1u) + 1u == t * 10u)
                g_ep = t;
        while (g_ep < t) { }
    }
    __syncthreads();
}

// A-barrier (blocks 0..115): arrive always, spin only if requested (block 0)
__device__ __forceinline__ void async_bar(unsigned t, bool spin) {
    __syncthreads();
    if (threadIdx.x == 0) {
        __threadfence();
        unsigned grp = (unsigned)blockIdx.x >> 4;            // 0..7
        unsigned sz  = (grp == 7) ? 4u : 16u;                // 116 = 7*16 + 4
        if (atomicAdd(&a_c1[grp], 1u) + 1u == t * sz)
            if (atomicAdd(&a_c2, 1u) + 1u == t * 8u)
                a_ep = t;
        if (spin) while (a_ep < t) { }
    }
    __syncthreads();
}

// B-barrier (blocks 116..147): all spin
__device__ __forceinline__ void bsync_bar(unsigned t) {
    __syncthreads();
    if (threadIdx.x == 0) {
        __threadfence();
        unsigned grp = ((unsigned)blockIdx.x - NA) >> 4;     // 0..1, 16 each
        if (atomicAdd(&b_c1[grp], 1u) + 1u == t * 16u)
            if (atomicAdd(&b_c2, 1u) + 1u == t * 2u)
                b_ep = t;
        while (b_ep < t) { }
    }
    __syncthreads();
}

__device__ __forceinline__ float warp_red(float v) {
    #pragma unroll
    for (int o = 16; o > 0; o >>= 1) v += __shfl_down_sync(0xffffffffu, v, o);
    return v;
}

// 2-way interleaved reduction: overlaps the SHFL latency chains
__device__ __forceinline__ void warp_red2(float& s0, float& s1) {
    #pragma unroll
    for (int o = 16; o > 0; o >>= 1) {
        s0 += __shfl_down_sync(0xffffffffu, s0, o);
        s1 += __shfl_down_sync(0xffffffffu, s1, o);
    }
}

__device__ __forceinline__ float dot4(const float4 w, const float4 a) {
    return fmaf(w.x, a.x, fmaf(w.y, a.y, fmaf(w.z, a.z, w.w * a.w)));
}

__device__ __forceinline__ float dot8h(uint4 q, const float4* __restrict__ s, int k) {
    float2 f0 = __half22float2(*(__half2*)&q.x);
    float2 f1 = __half22float2(*(__half2*)&q.y);
    float2 f2 = __half22float2(*(__half2*)&q.z);
    float2 f3 = __half22float2(*(__half2*)&q.w);
    float4 v0 = s[2*k], v1 = s[2*k+1];
    float r = fmaf(f0.x, v0.x, fmaf(f0.y, v0.y, fmaf(f1.x, v0.z, f1.y * v0.w)));
    return fmaf(f2.x, v1.x, fmaf(f2.y, v1.y, fmaf(f3.x, v1.z, fmaf(f3.y, v1.w, r))));
}

// register-activation variant: no smem reads in the hot loop
__device__ __forceinline__ float dot8h_reg(uint4 q, float4 v0, float4 v1) {
    float2 f0 = __half22float2(*(__half2*)&q.x);
    float2 f1 = __half22float2(*(__half2*)&q.y);
    float2 f2 = __half22float2(*(__half2*)&q.z);
    float2 f3 = __half22float2(*(__half2*)&q.w);
    float r = fmaf(f0.x, v0.x, fmaf(f0.y, v0.y, fmaf(f1.x, v0.z, f1.y * v0.w)));
    return fmaf(f2.x, v1.x, fmaf(f2.y, v1.y, fmaf(f3.x, v1.z, fmaf(f3.y, v1.w, r))));
}

__device__ __forceinline__ float row_dot(int r, int lane,
    float4 a0, float4 a1, float4 a2, float4 a3,
    float4 a4, float4 a5, float4 a6, float4 a7)
{
    const uint4* wr = g_outW + (size_t)r * H8;
    return dot8h_reg(wr[lane],      a0, a1)
         + dot8h_reg(wr[lane + 32], a2, a3)
         + dot8h_reg(wr[lane + 64], a4, a5)
         + dot8h_reg(wr[lane + 96], a6, a7);
}

// ---------------- the whole model (graph node 2) ----------------
__global__ void __launch_bounds__(NT, 1) model_kernel(
    const int*   __restrict__ seq,   const float* __restrict__ embeds,
    const float* __restrict__ ebih,  const float* __restrict__ ebhh,
    const float* __restrict__ dbih,  const float* __restrict__ dbhh,
    const float* __restrict__ outb,
    const float* __restrict__ v,     const float* __restrict__ w1,
    const float* __restrict__ w2,
    float* __restrict__ out, float* __restrict__ out_seq)
{
    const int b = blockIdx.x, tid = threadIdx.x;
    const int warp = tid >> 5, lane = tid & 31;
    const int gg_ = warp >> 3, uu_ = warp & 7;        // gate / unit ownership
    unsigned epg = 0, epa = 0, epb = 0;

    __shared__ float s_vec[2*H];
    __shared__ float s_h[H];
    __shared__ float s_sc[L];
    __shared__ float s_red[32];
    __shared__ float s_red2[32];
    __shared__ unsigned long long s_key[32];
    __shared__ float s_r2[NT];
    __shared__ float s_c[8];
    __shared__ int   s_idx;

    if (tid < 8) s_c[tid] = 0.f;

    // ---- embedding gather ----
    for (int t = b; t < L; t += NB) {
        int id = seq[t];
        const float* src = embeds + (size_t)id * H;
        for (int k = tid; k < H; k += NT) g_xemb[t*H + k] = src[k];
    }
    gsync(++epg);

    // ---- precompute eWih @ x(t) for all t (block-local rows; weights L1-hot) ----
    if (b < NG) {
        int j = b * 8 + uu_;
        int r = gg_ * H + j;
        const uint4* wi = g_eWih + (size_t)r * H8;
        float4* sx = (float4*)s_vec;
        for (int t = 0; t < L; t++) {
            const float4* xv = (const float4*)(g_xemb + t*H);
            for (int k = tid; k < H4; k += NT) sx[k] = xv[k];
            __syncthreads();
            float s = 0.f;
            #pragma unroll
            for (int k = lane; k < H8; k += 32) s += dot8h(wi[k], sx, k);
            s = warp_red(s);
            if (lane == 0) g_pih[t*4*H + r] = s;
            __syncthreads();
        }
    }
    // no gsync needed: each block consumes only its own g_pih rows

    // ---- encoder: 256 steps, 1 barrier each (Whh only; Wih part precomputed) ----
    for (int t = 0; t < L; t++) {
        if (b < NG) {
            const float4* hv = (const float4*)g_h[t & 1];
            float4* sh = (float4*)s_h;
            for (int k = tid; k < H4; k += NT) sh[k] = __ldcg(hv + k);
            __syncthreads();
            int j = b * 8 + uu_;
            int r = gg_ * H + j;
            const uint4* wh = g_eWhh + (size_t)r * H8;
            float s = 0.f;
            #pragma unroll
            for (int k = lane; k < H8; k += 32) s += dot8h(wh[k], sh, k);
            s = warp_red(s);
            if (lane == 0) s_red2[warp] = s + g_pih[t*4*H + r];
            __syncthreads();
            if (tid < 8) {
                int jj = b * 8 + tid;
                float gi = s_red2[tid]      + ebih[jj]       + ebhh[jj];
                float gf = s_red2[8 + tid]  + ebih[H + jj]   + ebhh[H + jj];
                float gG = s_red2[16 + tid] + ebih[2*H + jj] + ebhh[2*H + jj];
                float go = s_red2[24 + tid] + ebih[3*H + jj] + ebhh[3*H + jj];
                float i_ = 1.f / (1.f + expf(-gi));
                float f_ = 1.f / (1.f + expf(-gf));
                float o_ = 1.f / (1.f + expf(-go));
                float cn = f_ * s_c[tid] + i_ * tanhf(gG);
                float hn = o_ * tanhf(cn);
                s_c[tid] = cn;
                g_h[(t+1)&1][jj] = hn;
                g_E[t*H + jj] = hn;
                g_ET[jj*L + t] = hn;
            }
        }
        gsync(++epg);
    }

    // ---- Ew2 = E @ w2^T (one-time, blocks 0..127) ----
    if (b < NG) {
        for (int rr = 0; rr < 2; rr++) {
            int i = 2*b + rr;
            const float4* Er = (const float4*)(g_E + i*H);
            float4* sh = (float4*)s_h;
            for (int k = tid; k < H4; k += NT) sh[k] = Er[k];
            __syncthreads();
            for (int j = warp; j < H; j += 32) {
                const float4* wr = (const float4*)(w2 + (size_t)j * H);
                float s = 0.f;
                #pragma unroll 4
                for (int k = lane; k < H4; k += 32) s += dot4(wr[k], sh[k]);
                s = warp_red(s);
                if (lane == 0) g_Ew2[i*H + j] = s;
            }
            __syncthreads();
        }
    }
    gsync(++epg);

    // ---- prologue: w1h(h0) on b<NG + hhpart(h0) on b>=NA ----
    if (b < NG) {
        float4* sh = (float4*)s_h;
        const float4* hv = (const float4*)g_h[0];
        for (int k = tid; k < H4; k += NT) sh[k] = __ldcg(hv + k);
        __syncthreads();
        if (warp < 8) {
            int r = b * 8 + warp;
            const float4* wr = (const float4*)(w1 + (size_t)r * H);
            float s = 0.f;
            #pragma unroll 4
            for (int k = lane; k < H4; k += 32) s += dot4(wr[k], sh[k]);
            s = warp_red(s);
            if (lane == 0) g_w1h[r] = s;
        }
    }
    if (b >= NA) {
        float4* svv = (float4*)s_vec;
        const float4* hv = (const float4*)g_h[0];
        for (int k = tid; k < H4; k += NT) svv[k] = __ldcg(hv + k);
        __syncthreads();
        int wq = (b - NA) * 32 + warp;               // 0..1023
        #pragma unroll
        for (int rr = 0; rr < 4; rr += 2) {
            int r0 = wq * 4 + rr, r1 = r0 + 1;
            const uint4* wh0 = g_dWhh + (size_t)r0 * H8;
            const uint4* wh1 = g_dWhh + (size_t)r1 * H8;
            float s0 = 0.f, s1 = 0.f;
            #pragma unroll 4
            for (int k = lane; k < H8; k += 32) {
                s0 += dot8h(wh0[k], svv, k);
                s1 += dot8h(wh1[k], svv, k);
            }
            warp_red2(s0, s1);
            if (lane == 0) { g_hhpart[r0] = s0; g_hhpart[r1] = s1; }
        }
    }
    gsync(++epg);
    if (b < NG) {   // scores(0): rows 2b, 2b+1
        float4* sh = (float4*)s_h;
        const float4* wv = (const float4*)g_w1h;
        for (int k = tid; k < H4; k += NT) sh[k] = __ldcg(wv + k);
        __syncthreads();
        for (int rr = 0; rr < 2; rr++) {
            int i = 2*b + rr;
            float val = v[tid] * tanhf(s_h[tid] + __ldcg(&g_Ew2[i*H + tid]));
            val = warp_red(val);
            if (lane == 0) s_red[warp] = val;
            __syncthreads();
            if (warp == 0) {
                float x = warp_red(s_red[lane]);
                if (lane == 0) g_scores[i] = x;
            }
            __syncthreads();
        }
    }
    gsync(++epg);
    if (b < NG) {   // softmax + ctx(0): 8 elements per block
        if (tid < L) s_sc[tid] = __ldcg(g_scores + tid);
        __syncthreads();
        float mval = (tid < L) ? s_sc[tid] : -3.0e38f;
        #pragma unroll
        for (int o = 16; o > 0; o >>= 1)
            mval = fmaxf(mval, __shfl_down_sync(0xffffffffu, mval, o));
        if (lane == 0) s_red[warp] = mval;
        __syncthreads();
        if (tid == 0) {
            float mm = s_red[0];
            for (int w_ = 1; w_ < 32; w_++) mm = fmaxf(mm, s_red[w_]);
            s_red[0] = mm;
        }
        __syncthreads();
        float mx = s_red[0];
        float evv = (tid < L) ? expf(s_sc[tid] - mx) : 0.f;
        __syncthreads();
        if (tid < L) s_sc[tid] = evv;
        float sv2 = warp_red(evv);
        if (lane == 0) s_red[warp] = sv2;
        __syncthreads();
        if (tid == 0) {
            float ss = 0.f;
            for (int w_ = 0; w_ < 32; w_++) ss += s_red[w_];
            s_red[0] = 1.f / ss;
        }
        __syncthreads();
        float inv = s_red[0];
        int q = tid >> 7, ii = tid & 127;
        int j = b * 8 + q;
        float acc = s_sc[ii]       * g_ET[j*L + ii]
                  + s_sc[ii + 128] * g_ET[j*L + ii + 128];
        s_r2[tid] = acc;
        __syncthreads();
        for (int st = 64; st > 0; st >>= 1) {
            if (ii < st) s_r2[tid] += s_r2[tid + st];
            __syncthreads();
        }
        if (ii == 0) g_xin[H + j] = s_r2[tid] * inv;
    }
    gsync(++epg);

    // ---- decoder: 256 steps, 2 global barriers each ----
    for (int d = 0; d < L; d++) {
        const int pout = (d + 1) & 1;

        // gates: blocks 0..127 — Wih@xin only; Whh@h precomputed by B blocks
        if (b < NG) {
            float4* sv = (float4*)s_vec;
            const float4* xv = (const float4*)g_xin;
            for (int k = tid; k < 2*H4; k += NT) sv[k] = __ldcg(xv + k);
            __syncthreads();
            int j = b * 8 + uu_;
            int r = gg_ * H + j;
            const uint4* wi = g_dWih + (size_t)r * (2*H8);
            float s = 0.f;
            #pragma unroll 4
            for (int k = lane; k < 2*H8; k += 32) s += dot8h(wi[k], sv, k);
            s = warp_red(s);
            if (lane == 0) s_red2[warp] = s + __ldcg(&g_hhpart[r]);
            __syncthreads();
            if (tid < 8) {
                int jj = b * 8 + tid;
                float gi = s_red2[tid]      + dbih[jj]       + dbhh[jj];
                float gf = s_red2[8 + tid]  + dbih[H + jj]   + dbhh[H + jj];
                float gG = s_red2[16 + tid] + dbih[2*H + jj] + dbhh[2*H + jj];
                float go = s_red2[24 + tid] + dbih[3*H + jj] + dbhh[3*H + jj];
                float i_ = 1.f / (1.f + expf(-gi));
                float f_ = 1.f / (1.f + expf(-gf));
                float o_ = 1.f / (1.f + expf(-go));
                float cn = f_ * s_c[tid] + i_ * tanhf(gG);
                float hn = o_ * tanhf(cn);
                s_c[tid] = cn;
                g_h[pout][jj] = hn;
            }
        }
        gsync(++epg);

        if (b < NA) {
            // ---- A: logits(d) + argmax + feedback (2-row ILP) ----
            float4* sh = (float4*)s_h;
            const float4* hv = (const float4*)g_h[pout];
            for (int k = tid; k < H4; k += NT) sh[k] = __ldcg(hv + k);
            __syncthreads();
            float4 a0 = sh[2*lane],            a1 = sh[2*lane + 1];
            float4 a2 = sh[2*(lane+32)],       a3 = sh[2*(lane+32) + 1];
            float4 a4 = sh[2*(lane+64)],       a5 = sh[2*(lane+64) + 1];
            float4 a6 = sh[2*(lane+96)],       a7 = sh[2*(lane+96) + 1];
            float bestv = -3.0e38f; int bestr = 0;
            float* od = out + (size_t)d * V;
            const int base = b * 32 + warp;
            for (int r = base; r < V; r += NA * 64) {
                int r2 = r + NA * 32;
                bool ok2 = (r2 < V);
                float s0 = row_dot(r, lane, a0,a1,a2,a3,a4,a5,a6,a7);
                float s1 = ok2 ? row_dot(r2, lane, a0,a1,a2,a3,a4,a5,a6,a7) : 0.f;
                warp_red2(s0, s1);
                if (lane == 0) {
                    s0 += outb[r];
                    __stcs(od + r, s0);
                    if (s0 > bestv) { bestv = s0; bestr = r; }
                    if (ok2) {
                        s1 += outb[r2];
                        __stcs(od + r2, s1);
                        if (s1 > bestv) { bestv = s1; bestr = r2; }
                    }
                }
            }
            if (lane == 0) {
                unsigned u = __float_as_uint(bestv);
                u = (u & 0x80000000u) ? ~u : (u | 0x80000000u);
                s_key[warp] = ((unsigned long long)u << 32) |
                              (unsigned long long)(0xFFFFFFFFu - (unsigned)bestr);
            }
            __syncthreads();
            if (tid == 0) {
                unsigned long long kk = s_key[0];
                for (int w_ = 1; w_ < 32; w_++) if (s_key[w_] > kk) kk = s_key[w_];
                g_part[b] = kk;
            }
            ++epa;
            async_bar(epa, b == 0);
            if (b == 0) {
                if (warp == 0) {
                    unsigned long long kk = 0ull;
                    for (int q = lane; q < NA; q += 32) {
                        unsigned long long t2 = __ldcg((const unsigned long long*)(g_part + q));
                        if (t2 > kk) kk = t2;
                    }
                    #pragma unroll
                    for (int o = 16; o > 0; o >>= 1) {
                        unsigned long long ok = __shfl_down_sync(0xffffffffu, kk, o);
                        if (ok > kk) kk = ok;
                    }
                    if (lane == 0)
                        s_idx = (int)(0xFFFFFFFFu - (unsigned)(kk & 0xFFFFFFFFull));
                }
                __syncthreads();
                int idx = s_idx;
                float e = embeds[(size_t)idx * H + tid];
                g_xin[tid] = fmaxf(e, 0.f);                  // feedback for step d+1
                if (tid == 0 && out_seq) out_seq[d] = (float)idx;
            }
        } else {
            // ---- B (116..147): w1h -> scores(d+1) -> softmax+ctx(d+1) -> hhpart ----
            const int q = b - NA;                            // 0..31
            float4* sh = (float4*)s_h;
            float4* svv = (float4*)s_vec;
            const float4* hv = (const float4*)g_h[pout];
            for (int k = tid; k < H4; k += NT) {
                float4 hx = __ldcg(hv + k);
                sh[k] = hx; svv[k] = hx;                     // keep h copy in s_vec
            }
            __syncthreads();
            {   // w1h: 32 rows per block, warp per row
                int r = q * 32 + warp;
                const float4* wr = (const float4*)(w1 + (size_t)r * H);
                float s = 0.f;
                #pragma unroll 4
                for (int k = lane; k < H4; k += 32) s += dot4(wr[k], sh[k]);
                s = warp_red(s);
                if (lane == 0) g_w1h[r] = s;
            }
            bsync_bar(++epb);
            for (int k = tid; k < H4; k += NT) sh[k] = __ldcg((const float4*)g_w1h + k);
            __syncthreads();
            for (int rr = 0; rr < 8; rr++) {                 // scores: 8 rows per block
                int i = q * 8 + rr;
                float val = v[tid] * tanhf(s_h[tid] + __ldcg(&g_Ew2[i*H + tid]));
                val = warp_red(val);
                if (lane == 0) s_red[warp] = val;
                __syncthreads();
                if (warp == 0) {
                    float x = warp_red(s_red[lane]);
                    if (lane == 0) g_scores[i] = x;
                }
                __syncthreads();
            }
            bsync_bar(++epb);
            {   // softmax (redundant) + ctx: 32 elements per block, warp per element
                if (tid < L) s_sc[tid] = __ldcg(g_scores + tid);
                __syncthreads();
                float mval = (tid < L) ? s_sc[tid] : -3.0e38f;
                #pragma unroll
                for (int o = 16; o > 0; o >>= 1)
                    mval = fmaxf(mval, __shfl_down_sync(0xffffffffu, mval, o));
                if (lane == 0) s_red[warp] = mval;
                __syncthreads();
                if (tid == 0) {
                    float mm = s_red[0];
                    for (int w_ = 1; w_ < 32; w_++) mm = fmaxf(mm, s_red[w_]);
                    s_red[0] = mm;
                }
                __syncthreads();
                float mx = s_red[0];
                float evv = (tid < L) ? expf(s_sc[tid] - mx) : 0.f;
                __syncthreads();
                if (tid < L) s_sc[tid] = evv;
                float sv2 = warp_red(evv);
                if (lane == 0) s_red[warp] = sv2;
                __syncthreads();
                if (tid == 0) {
                    float ss = 0.f;
                    for (int w_ = 0; w_ < 32; w_++) ss += s_red[w_];
                    s_red[0] = 1.f / ss;
                }
                __syncthreads();
                float inv = s_red[0];
                int j = q * 32 + warp;
                float acc = 0.f;
                #pragma unroll 4
                for (int i = lane; i < L; i += 32)
                    acc += s_sc[i] * __ldcg(&g_ET[j*L + i]);
                acc = warp_red(acc);
                if (lane == 0) g_xin[H + j] = acc * inv;
            }
            {   // hhpart for next step's gates: 4 rows per warp (h copy in s_vec)
                int wq = q * 32 + warp;                      // 0..1023
                #pragma unroll
                for (int rr = 0; rr < 4; rr += 2) {
                    int r0 = wq * 4 + rr, r1 = r0 + 1;
                    const uint4* wh0 = g_dWhh + (size_t)r0 * H8;
                    const uint4* wh1 = g_dWhh + (size_t)r1 * H8;
                    float s0 = 0.f, s1 = 0.f;
                    #pragma unroll 4
                    for (int k = lane; k < H8; k += 32) {
                        s0 += dot8h(wh0[k], svv, k);
                        s1 += dot8h(wh1[k], svv, k);
                    }
                    warp_red2(s0, s1);
                    if (lane == 0) { g_hhpart[r0] = s0; g_hhpart[r1] = s1; }
                }
            }
        }
        gsync(++epg);
    }
}

// ---------------- launch: 2-node graph ----------------
extern "C" void kernel_launch(void* const* d_in, const int* in_sizes, int n_in,
                              void* d_out, int out_size)
{
    const int*   seq    = (const int*)  d_in[0];
    const float* embeds = (const float*)d_in[1];
    const float* eWih = (const float*)d_in[2],  *eWhh = (const float*)d_in[3];
    const float* ebih = (const float*)d_in[4],  *ebhh = (const float*)d_in[5];
    const float* dWih = (const float*)d_in[6],  *dWhh = (const float*)d_in[7];
    const float* dbih = (const float*)d_in[8],  *dbhh = (const float*)d_in[9];
    const float* outW = (const float*)d_in[10], *outb = (const float*)d_in[11];
    const float* v    = (const float*)d_in[12];
    const float* w1   = (const float*)d_in[13], *w2   = (const float*)d_in[14];

    float* out = (float*)d_out;
    float* out_seq = (out_size >= L*V + L) ? out + (size_t)L*V : nullptr;

    prep_kernel<<<2048, 256>>>(outW, dWih, dWhh, eWih, eWhh);
    model_kernel<<<NB, NT>>>(seq, embeds, ebih, ebhh,
                             dbih, dbhh, outb, v, w1, w2, out, out_seq);
}

// round 16
// speedup vs baseline: 1.1011x; 1.0982x over previous
#include <cuda_runtime.h>
#include <cuda_fp16.h>
#include <math.h>

#define H 1024
#define H4 256        // H/4 (float4 count)
#define H8 128        // H/8 (uint4-of-half count)
#define L 256
#define V 32000
#define NB 148        // one block per SM
#define NG 128        // blocks that own LSTM gate units
#define NA 116        // logits blocks (0..115)
#define NT 1024

// ---------------- persistent device state ----------------
__device__ float g_xemb[L*H];
__device__ float g_E[L*H];
__device__ float g_ET[H*L];             // E transposed: [j][t] for coalesced ctx
__device__ float g_Ew2[L*H];
__device__ float g_h[2][H];
__device__ float g_w1h[H];
__device__ float g_scores[L];
__device__ float g_xin[2*H];            // [relu(prev_emb) | ctx]
__device__ unsigned long long g_part[NA];

// tree barriers (monotonic, never reset)
__device__ unsigned g_c1[10], g_c2;  __device__ volatile unsigned g_ep;
__device__ unsigned a_c1[8],  a_c2;  __device__ volatile unsigned a_ep;
__device__ unsigned b_c1[2],  b_c2;  __device__ volatile unsigned b_ep;

// fp16 weight copies (static, no allocs)
__device__ uint4 g_outW[(size_t)V*H/8];
__device__ uint4 g_dWih[(size_t)4*H*2*H/8];
__device__ uint4 g_dWhh[(size_t)4*H*H/8];
__device__ uint4 g_eWih[(size_t)4*H*H/8];
__device__ uint4 g_eWhh[(size_t)4*H*H/8];

// ---------------- prep: init (block 0) + fp32->fp16 conversion (graph node 1) ----
__device__ __forceinline__ void cvt_range(uint2* dst, const float4* src,
                                          size_t n, size_t t0, size_t stride) {
    for (size_t i = t0; i < n; i += stride) {
        float4 f = src[i];
        __half2 a = __floats2half2_rn(f.x, f.y), b = __floats2half2_rn(f.z, f.w);
        dst[i] = make_uint2(*(unsigned*)&a, *(unsigned*)&b);
    }
}

__global__ void prep_kernel(const float* __restrict__ outW,
                            const float* __restrict__ dWih,
                            const float* __restrict__ dWhh,
                            const float* __restrict__ eWih,
                            const float* __restrict__ eWhh)
{
    if (blockIdx.x == 0) {                       // init block
        int t = threadIdx.x;
        if (t < 10) g_c1[t] = 0;
        if (t < 8)  a_c1[t] = 0;
        if (t < 2)  b_c1[t] = 0;
        if (t == 0) { g_c2 = 0; a_c2 = 0; b_c2 = 0; g_ep = 0; a_ep = 0; b_ep = 0; }
        for (int k = t; k < H; k += blockDim.x) {
            g_h[0][k] = 0.f; g_h[1][k] = 0.f;
            g_xin[k] = 0.f;  g_xin[H + k] = 0.f;
        }
    }
    size_t stride = (size_t)gridDim.x * blockDim.x;
    size_t t0 = (size_t)blockIdx.x * blockDim.x + threadIdx.x;
    cvt_range((uint2*)g_outW, (const float4*)outW, (size_t)V*H/4,     t0, stride);
    cvt_range((uint2*)g_dWih, (const float4*)dWih, (size_t)4*H*2*H/4, t0, stride);
    cvt_range((uint2*)g_dWhh, (const float4*)dWhh, (size_t)4*H*H/4,   t0, stride);
    cvt_range((uint2*)g_eWih, (const float4*)eWih, (size_t)4*H*H/4,   t0, stride);
    cvt_range((uint2*)g_eWhh, (const float4*)eWhh, (size_t)4*H*H/4,   t0, stride);
}

// ---------------- tree grid barrier: 10 groups of <=16 -> root of 10 ----------------
__device__ __forceinline__ void gsync(unsigned t) {
    __syncthreads();
    if (threadIdx.x == 0) {
        __threadfence();
        unsigned grp = (unsigned)blockIdx.x >> 4;            // 0..9
        unsigned sz  = (grp == 9) ? 4u : 16u;                // 148 = 9*16 + 4
        if (atomicAdd(&g_c1[grp], 1u) + 1u == t * sz)
            if (atomicAdd(&g_c2, 1u) + 1u == t * 10u)
                g_ep = t;
        while (g_ep < t) { }
    }
    __syncthreads();
}

// A-barrier (blocks 0..115): arrive always, spin only if requested (block 0)
__device__ __forceinline__ void async_bar(unsigned t, bool spin) {
    __syncthreads();
    if (threadIdx.x == 0) {
        __threadfence();
        unsigned grp = (unsigned)blockIdx.x >> 4;            // 0..7
        unsigned sz  = (grp == 7) ? 4u : 16u;                // 116 = 7*16 + 4
        if (atomicAdd(&a_c1[grp], 1u) + 1u == t * sz)
            if (atomicAdd(&a_c2, 1u) + 1u == t * 8u)
                a_ep = t;
        if (spin) while (a_ep < t) { }
    }
    __syncthreads();
}

// B-barrier (blocks 116..147): all spin
__device__ __forceinline__ void bsync_bar(unsigned t) {
    __syncthreads();
    if (threadIdx.x == 0) {
        __threadfence();
        unsigned grp = ((unsigned)blockIdx.x - NA) >> 4;     // 0..1, 16 each
        if (atomicAdd(&b_c1[grp], 1u) + 1u == t * 16u)
            if (atomicAdd(&b_c2, 1u) + 1u == t * 2u)
                b_ep = t;
        while (b_ep < t) { }
    }
    __syncthreads();
}

__device__ __forceinline__ float warp_red(float v) {
    #pragma unroll
    for (int o = 16; o > 0; o >>= 1) v += __shfl_down_sync(0xffffffffu, v, o);
    return v;
}

// interleaved reductions: overlap the SHFL latency chains
__device__ __forceinline__ void warp_red2(float& s0, float& s1) {
    #pragma unroll
    for (int o = 16; o > 0; o >>= 1) {
        s0 += __shfl_down_sync(0xffffffffu, s0, o);
        s1 += __shfl_down_sync(0xffffffffu, s1, o);
    }
}
__device__ __forceinline__ void warp_red4(float& s0, float& s1, float& s2, float& s3) {
    #pragma unroll
    for (int o = 16; o > 0; o >>= 1) {
        s0 += __shfl_down_sync(0xffffffffu, s0, o);
        s1 += __shfl_down_sync(0xffffffffu, s1, o);
        s2 += __shfl_down_sync(0xffffffffu, s2, o);
        s3 += __shfl_down_sync(0xffffffffu, s3, o);
    }
}

__device__ __forceinline__ float dot4(const float4 w, const float4 a) {
    return fmaf(w.x, a.x, fmaf(w.y, a.y, fmaf(w.z, a.z, w.w * a.w)));
}

__device__ __forceinline__ float dot8h(uint4 q, const float4* __restrict__ s, int k) {
    float2 f0 = __half22float2(*(__half2*)&q.x);
    float2 f1 = __half22float2(*(__half2*)&q.y);
    float2 f2 = __half22float2(*(__half2*)&q.z);
    float2 f3 = __half22float2(*(__half2*)&q.w);
    float4 v0 = s[2*k], v1 = s[2*k+1];
    float r = fmaf(f0.x, v0.x, fmaf(f0.y, v0.y, fmaf(f1.x, v0.z, f1.y * v0.w)));
    return fmaf(f2.x, v1.x, fmaf(f2.y, v1.y, fmaf(f3.x, v1.z, fmaf(f3.y, v1.w, r))));
}

// register-activation variant: no smem reads in the hot loop
__device__ __forceinline__ float dot8h_reg(uint4 q, float4 v0, float4 v1) {
    float2 f0 = __half22float2(*(__half2*)&q.x);
    float2 f1 = __half22float2(*(__half2*)&q.y);
    float2 f2 = __half22float2(*(__half2*)&q.z);
    float2 f3 = __half22float2(*(__half2*)&q.w);
    float r = fmaf(f0.x, v0.x, fmaf(f0.y, v0.y, fmaf(f1.x, v0.z, f1.y * v0.w)));
    return fmaf(f2.x, v1.x, fmaf(f2.y, v1.y, fmaf(f3.x, v1.z, fmaf(f3.y, v1.w, r))));
}

// logits row: .cg loads (no L1 allocation — zero reuse stream)
__device__ __forceinline__ float row_dot(int r, int lane,
    float4 a0, float4 a1, float4 a2, float4 a3,
    float4 a4, float4 a5, float4 a6, float4 a7)
{
    const uint4* wr = g_outW + (size_t)r * H8;
    return dot8h_reg(__ldcg(wr + lane),      a0, a1)
         + dot8h_reg(__ldcg(wr + lane + 32), a2, a3)
         + dot8h_reg(__ldcg(wr + lane + 64), a4, a5)
         + dot8h_reg(__ldcg(wr + lane + 96), a6, a7);
}

// ---------------- the whole model (graph node 2) ----------------
__global__ void __launch_bounds__(NT, 1) model_kernel(
    const int*   __restrict__ seq,   const float* __restrict__ embeds,
    const float* __restrict__ ebih,  const float* __restrict__ ebhh,
    const float* __restrict__ dbih,  const float* __restrict__ dbhh,
    const float* __restrict__ outb,
    const float* __restrict__ v,     const float* __restrict__ w1,
    const float* __restrict__ w2,
    float* __restrict__ out, float* __restrict__ out_seq)
{
    const int b = blockIdx.x, tid = threadIdx.x;
    const int warp = tid >> 5, lane = tid & 31;
    const int gg_ = warp >> 3, uu_ = warp & 7;        // gate / unit ownership
    unsigned epg = 0, epa = 0, epb = 0;

    __shared__ float s_vec[2*H];
    __shared__ float s_h[H];
    __shared__ float s_sc[L];
    __shared__ float s_red[32];
    __shared__ float s_red2[32];
    __shared__ unsigned long long s_key[32];
    __shared__ float s_r2[NT];
    __shared__ float s_c[8];
    __shared__ int   s_idx;

    if (tid < 8) s_c[tid] = 0.f;

    // ---- embedding gather ----
    for (int t = b; t < L; t += NB) {
        int id = seq[t];
        const float* src = embeds + (size_t)id * H;
        for (int k = tid; k < H; k += NT) g_xemb[t*H + k] = src[k];
    }
    gsync(++epg);

    // ---- encoder: 256 steps, 1 barrier each (fp16 weights, blocks 0..127) ----
    for (int t = 0; t < L; t++) {
        if (b < NG) {
            const float4* xv = (const float4*)(g_xemb + t*H);
            const float4* hv = (const float4*)g_h[t & 1];
            float4* sx = (float4*)s_vec;
            float4* sh = (float4*)s_h;
            for (int k = tid; k < H4; k += NT) { sx[k] = xv[k]; sh[k] = __ldcg(hv + k); }
            __syncthreads();
            int j = b * 8 + uu_;
            int r = gg_ * H + j;
            const uint4* wi = g_eWih + (size_t)r * H8;
            const uint4* wh = g_eWhh + (size_t)r * H8;
            float s = 0.f;
            #pragma unroll
            for (int k = lane; k < H8; k += 32) {
                s += dot8h(wi[k], sx, k);
                s += dot8h(wh[k], sh, k);
            }
            s = warp_red(s);
            if (lane == 0) s_red2[warp] = s;
            __syncthreads();
            if (tid < 8) {
                int jj = b * 8 + tid;
                float gi = s_red2[tid]      + ebih[jj]       + ebhh[jj];
                float gf = s_red2[8 + tid]  + ebih[H + jj]   + ebhh[H + jj];
                float gG = s_red2[16 + tid] + ebih[2*H + jj] + ebhh[2*H + jj];
                float go = s_red2[24 + tid] + ebih[3*H + jj] + ebhh[3*H + jj];
                float i_ = 1.f / (1.f + expf(-gi));
                float f_ = 1.f / (1.f + expf(-gf));
                float o_ = 1.f / (1.f + expf(-go));
                float cn = f_ * s_c[tid] + i_ * tanhf(gG);
                float hn = o_ * tanhf(cn);
                s_c[tid] = cn;
                g_h[(t+1)&1][jj] = hn;
                g_E[t*H + jj] = hn;
                g_ET[jj*L + t] = hn;
            }
        }
        gsync(++epg);
    }

    // ---- Ew2 = E @ w2^T (one-time, blocks 0..127) ----
    if (b < NG) {
        for (int rr = 0; rr < 2; rr++) {
            int i = 2*b + rr;
            const float4* Er = (const float4*)(g_E + i*H);
            float4* sh = (float4*)s_h;
            for (int k = tid; k < H4; k += NT) sh[k] = Er[k];
            __syncthreads();
            for (int j = warp; j < H; j += 32) {
                const float4* wr = (const float4*)(w2 + (size_t)j * H);
                float s = 0.f;
                #pragma unroll 4
                for (int k = lane; k < H4; k += 32) s += dot4(wr[k], sh[k]);
                s = warp_red(s);
                if (lane == 0) g_Ew2[i*H + j] = s;
            }
            __syncthreads();
        }
    }
    gsync(++epg);

    // ---- prologue for step 0: w1h, scores(0), ctx(0) (blocks 0..127) ----
    if (b < NG) {
        float4* sh = (float4*)s_h;
        const float4* hv = (const float4*)g_h[0];
        for (int k = tid; k < H4; k += NT) sh[k] = __ldcg(hv + k);
        __syncthreads();
        if (warp < 8) {
            int r = b * 8 + warp;
            const float4* wr = (const float4*)(w1 + (size_t)r * H);
            float s = 0.f;
            #pragma unroll 4
            for (int k = lane; k < H4; k += 32) s += dot4(wr[k], sh[k]);
            s = warp_red(s);
            if (lane == 0) g_w1h[r] = s;
        }
    }
    gsync(++epg);
    if (b < NG) {   // scores(0): rows 2b, 2b+1
        float4* sh = (float4*)s_h;
        const float4* wv = (const float4*)g_w1h;
        for (int k = tid; k < H4; k += NT) sh[k] = __ldcg(wv + k);
        __syncthreads();
        for (int rr = 0; rr < 2; rr++) {
            int i = 2*b + rr;
            float val = v[tid] * tanhf(s_h[tid] + __ldcg(&g_Ew2[i*H + tid]));
            val = warp_red(val);
            if (lane == 0) s_red[warp] = val;
            __syncthreads();
            if (warp == 0) {
                float x = warp_red(s_red[lane]);
                if (lane == 0) g_scores[i] = x;
            }
            __syncthreads();
        }
    }
    gsync(++epg);
    if (b < NG) {   // softmax + ctx(0): 8 elements per block
        if (tid < L) s_sc[tid] = __ldcg(g_scores + tid);
        __syncthreads();
        float mval = (tid < L) ? s_sc[tid] : -3.0e38f;
        #pragma unroll
        for (int o = 16; o > 0; o >>= 1)
            mval = fmaxf(mval, __shfl_down_sync(0xffffffffu, mval, o));
        if (lane == 0) s_red[warp] = mval;
        __syncthreads();
        if (tid == 0) {
            float mm = s_red[0];
            for (int w_ = 1; w_ < 32; w_++) mm = fmaxf(mm, s_red[w_]);
            s_red[0] = mm;
        }
        __syncthreads();
        float mx = s_red[0];
        float evv = (tid < L) ? expf(s_sc[tid] - mx) : 0.f;
        __syncthreads();
        if (tid < L) s_sc[tid] = evv;
        float sv2 = warp_red(evv);
        if (lane == 0) s_red[warp] = sv2;
        __syncthreads();
        if (tid == 0) {
            float ss = 0.f;
            for (int w_ = 0; w_ < 32; w_++) ss += s_red[w_];
            s_red[0] = 1.f / ss;
        }
        __syncthreads();
        float inv = s_red[0];
        int q = tid >> 7, ii = tid & 127;
        int j = b * 8 + q;
        float acc = s_sc[ii]       * g_ET[j*L + ii]
                  + s_sc[ii + 128] * g_ET[j*L + ii + 128];
        s_r2[tid] = acc;
        __syncthreads();
        for (int st = 64; st > 0; st >>= 1) {
            if (ii < st) s_r2[tid] += s_r2[tid + st];
            __syncthreads();
        }
        if (ii == 0) g_xin[H + j] = s_r2[tid] * inv;
    }
    gsync(++epg);

    // ---- decoder: 256 steps, 2 global barriers each ----
    for (int d = 0; d < L; d++) {
        const int pin = d & 1, pout = (d + 1) & 1;

        // gates: blocks 0..127 (fp16 weights, block-local combine)
        if (b < NG) {
            float4* sv = (float4*)s_vec;
            float4* sh = (float4*)s_h;
            const float4* xv = (const float4*)g_xin;
            const float4* hv = (const float4*)g_h[pin];
            for (int k = tid; k < 2*H4; k += NT) sv[k] = __ldcg(xv + k);
            for (int k = tid; k < H4;   k += NT) sh[k] = __ldcg(hv + k);
            __syncthreads();
            int j = b * 8 + uu_;
            int r = gg_ * H + j;
            const uint4* wi = g_dWih + (size_t)r * (2*H8);
            const uint4* wh = g_dWhh + (size_t)r * H8;
            float s = 0.f;
            #pragma unroll 4
            for (int k = lane; k < 2*H8; k += 32) s += dot8h(wi[k], sv, k);
            #pragma unroll 4
            for (int k = lane; k < H8;   k += 32) s += dot8h(wh[k], sh, k);
            s = warp_red(s);
            if (lane == 0) s_red2[warp] = s;
            __syncthreads();
            if (tid < 8) {
                int jj = b * 8 + tid;
                float gi = s_red2[tid]      + dbih[jj]       + dbhh[jj];
                float gf = s_red2[8 + tid]  + dbih[H + jj]   + dbhh[H + jj];
                float gG = s_red2[16 + tid] + dbih[2*H + jj] + dbhh[2*H + jj];
                float go = s_red2[24 + tid] + dbih[3*H + jj] + dbhh[3*H + jj];
                float i_ = 1.f / (1.f + expf(-gi));
                float f_ = 1.f / (1.f + expf(-gf));
                float o_ = 1.f / (1.f + expf(-go));
                float cn = f_ * s_c[tid] + i_ * tanhf(gG);
                float hn = o_ * tanhf(cn);
                s_c[tid] = cn;
                g_h[pout][jj] = hn;
            }
        }
        gsync(++epg);

        if (b < NA) {
            // ---- A: logits(d) + argmax + feedback (4-row ILP, .cg streams) ----
            float4* sh = (float4*)s_h;
            const float4* hv = (const float4*)g_h[pout];
            for (int k = tid; k < H4; k += NT) sh[k] = __ldcg(hv + k);
            __syncthreads();
            float4 a0 = sh[2*lane],            a1 = sh[2*lane + 1];
            float4 a2 = sh[2*(lane+32)],       a3 = sh[2*(lane+32) + 1];
            float4 a4 = sh[2*(lane+64)],       a5 = sh[2*(lane+64) + 1];
            float4 a6 = sh[2*(lane+96)],       a7 = sh[2*(lane+96) + 1];
            float bestv = -3.0e38f; int bestr = 0;
            float* od = out + (size_t)d * V;
            const int base = b * 32 + warp;      // warp-row id in [0, 3712)
            for (int r = base; r < V; r += NA * 128) {
                int r1 = r  + NA * 32;
                int r2 = r1 + NA * 32;
                int r3 = r2 + NA * 32;
                bool ok1 = (r1 < V), ok2 = (r2 < V), ok3 = (r3 < V);
                float s0 = row_dot(r, lane, a0,a1,a2,a3,a4,a5,a6,a7);
                float s1 = ok1 ? row_dot(r1, lane, a0,a1,a2,a3,a4,a5,a6,a7) : 0.f;
                float s2 = ok2 ? row_dot(r2, lane, a0,a1,a2,a3,a4,a5,a6,a7) : 0.f;
                float s3 = ok3 ? row_dot(r3, lane, a0,a1,a2,a3,a4,a5,a6,a7) : 0.f;
                warp_red4(s0, s1, s2, s3);
                if (lane == 0) {
                    s0 += outb[r];  __stcs(od + r, s0);
                    if (s0 > bestv) { bestv = s0; bestr = r; }
                    if (ok1) {
                        s1 += outb[r1]; __stcs(od + r1, s1);
                        if (s1 > bestv) { bestv = s1; bestr = r1; }
                    }
                    if (ok2) {
                        s2 += outb[r2]; __stcs(od + r2, s2);
                        if (s2 > bestv) { bestv = s2; bestr = r2; }
                    }
                    if (ok3) {
                        s3 += outb[r3]; __stcs(od + r3, s3);
                        if (s3 > bestv) { bestv = s3; bestr = r3; }
                    }
                }
            }
            if (lane == 0) {
                unsigned u = __float_as_uint(bestv);
                u = (u & 0x80000000u) ? ~u : (u | 0x80000000u);
                s_key[warp] = ((unsigned long long)u << 32) |
                              (unsigned long long)(0xFFFFFFFFu - (unsigned)bestr);
            }
            __syncthreads();
            if (tid == 0) {
                unsigned long long kk = s_key[0];
                for (int w_ = 1; w_ < 32; w_++) if (s_key[w_] > kk) kk = s_key[w_];
                g_part[b] = kk;
            }
            ++epa;
            async_bar(epa, b == 0);
            if (b == 0) {
                if (warp == 0) {
                    unsigned long long kk = 0ull;
                    for (int q = lane; q < NA; q += 32) {
                        unsigned long long t2 = __ldcg((const unsigned long long*)(g_part + q));
                        if (t2 > kk) kk = t2;
                    }
                    #pragma unroll
                    for (int o = 16; o > 0; o >>= 1) {
                        unsigned long long ok = __shfl_down_sync(0xffffffffu, kk, o);
                        if (ok > kk) kk = ok;
                    }
                    if (lane == 0)
                        s_idx = (int)(0xFFFFFFFFu - (unsigned)(kk & 0xFFFFFFFFull));
                }
                __syncthreads();
                int idx = s_idx;
                float e = embeds[(size_t)idx * H + tid];
                g_xin[tid] = fmaxf(e, 0.f);                  // feedback for step d+1
                if (tid == 0 && out_seq) out_seq[d] = (float)idx;
            }
        } else {
            // ---- B (blocks 116..147): w1h -> scores(d+1) -> softmax+ctx(d+1) ----
            const int q = b - NA;                            // 0..31
            float4* sh = (float4*)s_h;
            const float4* hv = (const float4*)g_h[pout];
            for (int k = tid; k < H4; k += NT) sh[k] = __ldcg(hv + k);
            __syncthreads();
            {   // w1h: 32 rows per block, warp per row
                int r = q * 32 + warp;
                const float4* wr = (const float4*)(w1 + (size_t)r * H);
                float s = 0.f;
                #pragma unroll 4
                for (int k = lane; k < H4; k += 32) s += dot4(wr[k], sh[k]);
                s = warp_red(s);
                if (lane == 0) g_w1h[r] = s;
            }
            bsync_bar(++epb);
            for (int k = tid; k < H4; k += NT) sh[k] = __ldcg((const float4*)g_w1h + k);
            __syncthreads();
            for (int rr = 0; rr < 8; rr++) {                 // scores: 8 rows per block
                int i = q * 8 + rr;
                float val = v[tid] * tanhf(s_h[tid] + __ldcg(&g_Ew2[i*H + tid]));
                val = warp_red(val);
                if (lane == 0) s_red[warp] = val;
                __syncthreads();
                if (warp == 0) {
                    float x = warp_red(s_red[lane]);
                    if (lane == 0) g_scores[i] = x;
                }
                __syncthreads();
            }
            bsync_bar(++epb);
            {   // softmax (redundant) + ctx: 32 elements per block, warp per element
                if (tid < L) s_sc[tid] = __ldcg(g_scores + tid);
                __syncthreads();
                float mval = (tid < L) ? s_sc[tid] : -3.0e38f;
                #pragma unroll
                for (int o = 16; o > 0; o >>= 1)
                    mval = fmaxf(mval, __shfl_down_sync(0xffffffffu, mval, o));
                if (lane == 0) s_red[warp] = mval;
                __syncthreads();
                if (tid == 0) {
                    float mm = s_red[0];
                    for (int w_ = 1; w_ < 32; w_++) mm = fmaxf(mm, s_red[w_]);
                    s_red[0] = mm;
                }
                __syncthreads();
                float mx = s_red[0];
                float evv = (tid < L) ? expf(s_sc[tid] - mx) : 0.f;
                __syncthreads();
                if (tid < L) s_sc[tid] = evv;
                float sv2 = warp_red(evv);
                if (lane == 0) s_red[warp] = sv2;
                __syncthreads();
                if (tid == 0) {
                    float ss = 0.f;
                    for (int w_ = 0; w_ < 32; w_++) ss += s_red[w_];
                    s_red[0] = 1.f / ss;
                }
                __syncthreads();
                float inv = s_red[0];
                int j = q * 32 + warp;
                float acc = 0.f;
                #pragma unroll 4
                for (int i = lane; i < L; i += 32)
                    acc += s_sc[i] * __ldcg(&g_ET[j*L + i]);
                acc = warp_red(acc);
                if (lane == 0) g_xin[H + j] = acc * inv;
            }
        }
        gsync(++epg);
    }
}

// ---------------- launch: 2-node graph ----------------
extern "C" void kernel_launch(void* const* d_in, const int* in_sizes, int n_in,
                              void* d_out, int out_size)
{
    const int*   seq    = (const int*)  d_in[0];
    const float* embeds = (const float*)d_in[1];
    const float* eWih = (const float*)d_in[2],  *eWhh = (const float*)d_in[3];
    const float* ebih = (const float*)d_in[4],  *ebhh = (const float*)d_in[5];
    const float* dWih = (const float*)d_in[6],  *dWhh = (const float*)d_in[7];
    const float* dbih = (const float*)d_in[8],  *dbhh = (const float*)d_in[9];
    const float* outW = (const float*)d_in[10], *outb = (const float*)d_in[11];
    const float* v    = (const float*)d_in[12];
    const float* w1   = (const float*)d_in[13], *w2   = (const float*)d_in[14];

    float* out = (float*)d_out;
    float* out_seq = (out_size >= L*V + L) ? out + (size_t)L*V : nullptr;

    prep_kernel<<<2048, 256>>>(outW, dWih, dWhh, eWih, eWhh);
    model_kernel<<<NB, NT>>>(seq, embeds, ebih, ebhh,
                             dbih, dbhh, outb, v, w1, w2, out, out_seq);
}

// round 17
// speedup vs baseline: 1.2151x; 1.1036x over previous
#include <cuda_runtime.h>
#include <cuda_fp16.h>
#include <math.h>

#define H 1024
#define H4 256        // H/4 (float4 count)
#define H8 128        // H/8 (uint4-of-half count)
#define L 256
#define V 32000
#define NB 148        // one block per SM
#define NG 128        // blocks that own LSTM gate units
#define NA 132        // logits blocks (0..131); B = 16 attention blocks
#define NT 1024

// ---------------- persistent device state ----------------
__device__ float g_xemb[L*H];
__device__ float g_E[L*H];
__device__ float g_ET[H*L];             // E transposed: [j][t] for coalesced ctx
__device__ float g_Ew2[L*H];
__device__ float g_h[2][H];
__device__ float g_w1h[H];
__device__ float g_scores[L];
__device__ float g_xin[2*H];            // [relu(prev_emb) | ctx]
__device__ unsigned long long g_part[NA];

// tree barriers (monotonic, never reset)
__device__ unsigned g_c1[10], g_c2;  __device__ volatile unsigned g_ep;
__device__ unsigned a_c1[9],  a_c2;  __device__ volatile unsigned a_ep;
__device__ unsigned b_c1[1];         __device__ volatile unsigned b_ep;

// fp16 weight copies (static, no allocs)
__device__ uint4 g_outW[(size_t)V*H/8];
__device__ uint4 g_dWih[(size_t)4*H*2*H/8];
__device__ uint4 g_dWhh[(size_t)4*H*H/8];
__device__ uint4 g_eWih[(size_t)4*H*H/8];
__device__ uint4 g_eWhh[(size_t)4*H*H/8];

// ---------------- prep: init (block 0) + fp32->fp16 conversion (graph node 1) ----
__device__ __forceinline__ void cvt_range(uint2* dst, const float4* src,
                                          size_t n, size_t t0, size_t stride) {
    for (size_t i = t0; i < n; i += stride) {
        float4 f = src[i];
        __half2 a = __floats2half2_rn(f.x, f.y), b = __floats2half2_rn(f.z, f.w);
        dst[i] = make_uint2(*(unsigned*)&a, *(unsigned*)&b);
    }
}

__global__ void prep_kernel(const float* __restrict__ outW,
                            const float* __restrict__ dWih,
                            const float* __restrict__ dWhh,
                            const float* __restrict__ eWih,
                            const float* __restrict__ eWhh)
{
    if (blockIdx.x == 0) {                       // init block
        int t = threadIdx.x;
        if (t < 10) g_c1[t] = 0;
        if (t < 9)  a_c1[t] = 0;
        if (t < 1)  b_c1[t] = 0;
        if (t == 0) { g_c2 = 0; a_c2 = 0; g_ep = 0; a_ep = 0; b_ep = 0; }
        for (int k = t; k < H; k += blockDim.x) {
            g_h[0][k] = 0.f; g_h[1][k] = 0.f;
            g_xin[k] = 0.f;  g_xin[H + k] = 0.f;
        }
    }
    size_t stride = (size_t)gridDim.x * blockDim.x;
    size_t t0 = (size_t)blockIdx.x * blockDim.x + threadIdx.x;
    cvt_range((uint2*)g_outW, (const float4*)outW, (size_t)V*H/4,     t0, stride);
    cvt_range((uint2*)g_dWih, (const float4*)dWih, (size_t)4*H*2*H/4, t0, stride);
    cvt_range((uint2*)g_dWhh, (const float4*)dWhh, (size_t)4*H*H/4,   t0, stride);
    cvt_range((uint2*)g_eWih, (const float4*)eWih, (size_t)4*H*H/4,   t0, stride);
    cvt_range((uint2*)g_eWhh, (const float4*)eWhh, (size_t)4*H*H/4,   t0, stride);
}

// ---------------- tree grid barrier: 10 groups of <=16 -> root of 10 ----------------
__device__ __forceinline__ void gsync(unsigned t) {
    __syncthreads();
    if (threadIdx.x == 0) {
        __threadfence();
        unsigned grp = (unsigned)blockIdx.x >> 4;            // 0..9
        unsigned sz  = (grp == 9) ? 4u : 16u;                // 148 = 9*16 + 4
        if (atomicAdd(&g_c1[grp], 1u) + 1u == t * sz)
            if (atomicAdd(&g_c2, 1u) + 1u == t * 10u)
                g_ep = t;
        while (g_ep < t) { }
    }
    __syncthreads();
}

// A-barrier (blocks 0..131): arrive always, spin only if requested (block 0)
__device__ __forceinline__ void async_bar(unsigned t, bool spin) {
    __syncthreads();
    if (threadIdx.x == 0) {
        __threadfence();
        unsigned grp = (unsigned)blockIdx.x >> 4;            // 0..8
        unsigned sz  = (grp == 8) ? 4u : 16u;                // 132 = 8*16 + 4
        if (atomicAdd(&a_c1[grp], 1u) + 1u == t * sz)
            if (atomicAdd(&a_c2, 1u) + 1u == t * 9u)
                a_ep = t;
        if (spin) while (a_ep < t) { }
    }
    __syncthreads();
}

// B-barrier (blocks 132..147, 16 blocks): single level, all spin
__device__ __forceinline__ void bsync_bar(unsigned t) {
    __syncthreads();
    if (threadIdx.x == 0) {
        __threadfence();
        if (atomicAdd(&b_c1[0], 1u) + 1u == t * 16u)
            b_ep = t;
        while (b_ep < t) { }
    }
    __syncthreads();
}

__device__ __forceinline__ float warp_red(float v) {
    #pragma unroll
    for (int o = 16; o > 0; o >>= 1) v += __shfl_down_sync(0xffffffffu, v, o);
    return v;
}

// 2-way interleaved reduction: overlaps the SHFL latency chains
__device__ __forceinline__ void warp_red2(float& s0, float& s1) {
    #pragma unroll
    for (int o = 16; o > 0; o >>= 1) {
        s0 += __shfl_down_sync(0xffffffffu, s0, o);
        s1 += __shfl_down_sync(0xffffffffu, s1, o);
    }
}

__device__ __forceinline__ float dot4(const float4 w, const float4 a) {
    return fmaf(w.x, a.x, fmaf(w.y, a.y, fmaf(w.z, a.z, w.w * a.w)));
}

__device__ __forceinline__ float dot8h(uint4 q, const float4* __restrict__ s, int k) {
    float2 f0 = __half22float2(*(__half2*)&q.x);
    float2 f1 = __half22float2(*(__half2*)&q.y);
    float2 f2 = __half22float2(*(__half2*)&q.z);
    float2 f3 = __half22float2(*(__half2*)&q.w);
    float4 v0 = s[2*k], v1 = s[2*k+1];
    float r = fmaf(f0.x, v0.x, fmaf(f0.y, v0.y, fmaf(f1.x, v0.z, f1.y * v0.w)));
    return fmaf(f2.x, v1.x, fmaf(f2.y, v1.y, fmaf(f3.x, v1.z, fmaf(f3.y, v1.w, r))));
}

// register-activation variant: no smem reads in the hot loop
__device__ __forceinline__ float dot8h_reg(uint4 q, float4 v0, float4 v1) {
    float2 f0 = __half22float2(*(__half2*)&q.x);
    float2 f1 = __half22float2(*(__half2*)&q.y);
    float2 f2 = __half22float2(*(__half2*)&q.z);
    float2 f3 = __half22float2(*(__half2*)&q.w);
    float r = fmaf(f0.x, v0.x, fmaf(f0.y, v0.y, fmaf(f1.x, v0.z, f1.y * v0.w)));
    return fmaf(f2.x, v1.x, fmaf(f2.y, v1.y, fmaf(f3.x, v1.z, fmaf(f3.y, v1.w, r))));
}

// logits row: default loads (cross-step L1 hits on each block's fixed rows)
__device__ __forceinline__ float row_dot(int r, int lane,
    float4 a0, float4 a1, float4 a2, float4 a3,
    float4 a4, float4 a5, float4 a6, float4 a7)
{
    const uint4* wr = g_outW + (size_t)r * H8;
    return dot8h_reg(wr[lane],      a0, a1)
         + dot8h_reg(wr[lane + 32], a2, a3)
         + dot8h_reg(wr[lane + 64], a4, a5)
         + dot8h_reg(wr[lane + 96], a6, a7);
}

// ---------------- the whole model (graph node 2) ----------------
__global__ void __launch_bounds__(NT, 1) model_kernel(
    const int*   __restrict__ seq,   const float* __restrict__ embeds,
    const float* __restrict__ ebih,  const float* __restrict__ ebhh,
    const float* __restrict__ dbih,  const float* __restrict__ dbhh,
    const float* __restrict__ outb,
    const float* __restrict__ v,     const float* __restrict__ w1,
    const float* __restrict__ w2,
    float* __restrict__ out, float* __restrict__ out_seq)
{
    const int b = blockIdx.x, tid = threadIdx.x;
    const int warp = tid >> 5, lane = tid & 31;
    const int gg_ = warp >> 3, uu_ = warp & 7;        // gate / unit ownership
    unsigned epg = 0, epa = 0, epb = 0;

    __shared__ float s_vec[2*H];
    __shared__ float s_h[H];
    __shared__ float s_sc[L];
    __shared__ float s_red[32];
    __shared__ float s_red2[32];
    __shared__ unsigned long long s_key[32];
    __shared__ float s_r2[NT];
    __shared__ float s_c[8];
    __shared__ int   s_idx;

    if (tid < 8) s_c[tid] = 0.f;

    // ---- embedding gather ----
    for (int t = b; t < L; t += NB) {
        int id = seq[t];
        const float* src = embeds + (size_t)id * H;
        for (int k = tid; k < H; k += NT) g_xemb[t*H + k] = src[k];
    }
    gsync(++epg);

    // ---- encoder: 256 steps, 1 barrier each (fp16 weights, blocks 0..127) ----
    for (int t = 0; t < L; t++) {
        if (b < NG) {
            const float4* xv = (const float4*)(g_xemb + t*H);
            const float4* hv = (const float4*)g_h[t & 1];
            float4* sx = (float4*)s_vec;
            float4* sh = (float4*)s_h;
            for (int k = tid; k < H4; k += NT) { sx[k] = xv[k]; sh[k] = __ldcg(hv + k); }
            __syncthreads();
            int j = b * 8 + uu_;
            int r = gg_ * H + j;
            const uint4* wi = g_eWih + (size_t)r * H8;
            const uint4* wh = g_eWhh + (size_t)r * H8;
            float s = 0.f;
            #pragma unroll
            for (int k = lane; k < H8; k += 32) {
                s += dot8h(wi[k], sx, k);
                s += dot8h(wh[k], sh, k);
            }
            s = warp_red(s);
            if (lane == 0) s_red2[warp] = s;
            __syncthreads();
            if (tid < 8) {
                int jj = b * 8 + tid;
                float gi = s_red2[tid]      + ebih[jj]       + ebhh[jj];
                float gf = s_red2[8 + tid]  + ebih[H + jj]   + ebhh[H + jj];
                float gG = s_red2[16 + tid] + ebih[2*H + jj] + ebhh[2*H + jj];
                float go = s_red2[24 + tid] + ebih[3*H + jj] + ebhh[3*H + jj];
                float i_ = 1.f / (1.f + expf(-gi));
                float f_ = 1.f / (1.f + expf(-gf));
                float o_ = 1.f / (1.f + expf(-go));
                float cn = f_ * s_c[tid] + i_ * tanhf(gG);
                float hn = o_ * tanhf(cn);
                s_c[tid] = cn;
                g_h[(t+1)&1][jj] = hn;
                g_E[t*H + jj] = hn;
                g_ET[jj*L + t] = hn;
            }
        }
        gsync(++epg);
    }

    // ---- Ew2 = E @ w2^T (one-time, blocks 0..127) ----
    if (b < NG) {
        for (int rr = 0; rr < 2; rr++) {
            int i = 2*b + rr;
            const float4* Er = (const float4*)(g_E + i*H);
            float4* sh = (float4*)s_h;
            for (int k = tid; k < H4; k += NT) sh[k] = Er[k];
            __syncthreads();
            for (int j = warp; j < H; j += 32) {
                const float4* wr = (const float4*)(w2 + (size_t)j * H);
                float s = 0.f;
                #pragma unroll 4
                for (int k = lane; k < H4; k += 32) s += dot4(wr[k], sh[k]);
                s = warp_red(s);
                if (lane == 0) g_Ew2[i*H + j] = s;
            }
            __syncthreads();
        }
    }
    gsync(++epg);

    // ---- prologue for step 0: w1h, scores(0), ctx(0) (blocks 0..127) ----
    if (b < NG) {
        float4* sh = (float4*)s_h;
        const float4* hv = (const float4*)g_h[0];
        for (int k = tid; k < H4; k += NT) sh[k] = __ldcg(hv + k);
        __syncthreads();
        if (warp < 8) {
            int r = b * 8 + warp;
            const float4* wr = (const float4*)(w1 + (size_t)r * H);
            float s = 0.f;
            #pragma unroll 4
            for (int k = lane; k < H4; k += 32) s += dot4(wr[k], sh[k]);
            s = warp_red(s);
            if (lane == 0) g_w1h[r] = s;
        }
    }
    gsync(++epg);
    if (b < NG) {   // scores(0): rows 2b, 2b+1
        float4* sh = (float4*)s_h;
        const float4* wv = (const float4*)g_w1h;
        for (int k = tid; k < H4; k += NT) sh[k] = __ldcg(wv + k);
        __syncthreads();
        for (int rr = 0; rr < 2; rr++) {
            int i = 2*b + rr;
            float val = v[tid] * tanhf(s_h[tid] + __ldcg(&g_Ew2[i*H + tid]));
            val = warp_red(val);
            if (lane == 0) s_red[warp] = val;
            __syncthreads();
            if (warp == 0) {
                float x = warp_red(s_red[lane]);
                if (lane == 0) g_scores[i] = x;
            }
            __syncthreads();
        }
    }
    gsync(++epg);
    if (b < NG) {   // softmax + ctx(0): 8 elements per block
        if (tid < L) s_sc[tid] = __ldcg(g_scores + tid);
        __syncthreads();
        float mval = (tid < L) ? s_sc[tid] : -3.0e38f;
        #pragma unroll
        for (int o = 16; o > 0; o >>= 1)
            mval = fmaxf(mval, __shfl_down_sync(0xffffffffu, mval, o));
        if (lane == 0) s_red[warp] = mval;
        __syncthreads();
        if (tid == 0) {
            float mm = s_red[0];
            for (int w_ = 1; w_ < 32; w_++) mm = fmaxf(mm, s_red[w_]);
            s_red[0] = mm;
        }
        __syncthreads();
        float mx = s_red[0];
        float evv = (tid < L) ? expf(s_sc[tid] - mx) : 0.f;
        __syncthreads();
        if (tid < L) s_sc[tid] = evv;
        float sv2 = warp_red(evv);
        if (lane == 0) s_red[warp] = sv2;
        __syncthreads();
        if (tid == 0) {
            float ss = 0.f;
            for (int w_ = 0; w_ < 32; w_++) ss += s_red[w_];
            s_red[0] = 1.f / ss;
        }
        __syncthreads();
        float inv = s_red[0];
        int q = tid >> 7, ii = tid & 127;
        int j = b * 8 + q;
        float acc = s_sc[ii]       * g_ET[j*L + ii]
                  + s_sc[ii + 128] * g_ET[j*L + ii + 128];
        s_r2[tid] = acc;
        __syncthreads();
        for (int st = 64; st > 0; st >>= 1) {
            if (ii < st) s_r2[tid] += s_r2[tid + st];
            __syncthreads();
        }
        if (ii == 0) g_xin[H + j] = s_r2[tid] * inv;
    }
    gsync(++epg);

    // ---- decoder: 256 steps, 2 global barriers each ----
    for (int d = 0; d < L; d++) {
        const int pin = d & 1, pout = (d + 1) & 1;

        // gates: blocks 0..127 (fp16 weights, block-local combine)
        if (b < NG) {
            float4* sv = (float4*)s_vec;
            float4* sh = (float4*)s_h;
            const float4* xv = (const float4*)g_xin;
            const float4* hv = (const float4*)g_h[pin];
            for (int k = tid; k < 2*H4; k += NT) sv[k] = __ldcg(xv + k);
            for (int k = tid; k < H4;   k += NT) sh[k] = __ldcg(hv + k);
            __syncthreads();
            int j = b * 8 + uu_;
            int r = gg_ * H + j;
            const uint4* wi = g_dWih + (size_t)r * (2*H8);
            const uint4* wh = g_dWhh + (size_t)r * H8;
            float s = 0.f;
            #pragma unroll 4
            for (int k = lane; k < 2*H8; k += 32) s += dot8h(wi[k], sv, k);
            #pragma unroll 4
            for (int k = lane; k < H8;   k += 32) s += dot8h(wh[k], sh, k);
            s = warp_red(s);
            if (lane == 0) s_red2[warp] = s;
            __syncthreads();
            if (tid < 8) {
                int jj = b * 8 + tid;
                float gi = s_red2[tid]      + dbih[jj]       + dbhh[jj];
                float gf = s_red2[8 + tid]  + dbih[H + jj]   + dbhh[H + jj];
                float gG = s_red2[16 + tid] + dbih[2*H + jj] + dbhh[2*H + jj];
                float go = s_red2[24 + tid] + dbih[3*H + jj] + dbhh[3*H + jj];
                float i_ = 1.f / (1.f + expf(-gi));
                float f_ = 1.f / (1.f + expf(-gf));
                float o_ = 1.f / (1.f + expf(-go));
                float cn = f_ * s_c[tid] + i_ * tanhf(gG);
                float hn = o_ * tanhf(cn);
                s_c[tid] = cn;
                g_h[pout][jj] = hn;
            }
        }
        gsync(++epg);

        if (b < NA) {
            // ---- A: logits(d) + argmax + feedback (2-row ILP, default loads) ----
            float4* sh = (float4*)s_h;
            const float4* hv = (const float4*)g_h[pout];
            for (int k = tid; k < H4; k += NT) sh[k] = __ldcg(hv + k);
            __syncthreads();
            float4 a0 = sh[2*lane],            a1 = sh[2*lane + 1];
            float4 a2 = sh[2*(lane+32)],       a3 = sh[2*(lane+32) + 1];
            float4 a4 = sh[2*(lane+64)],       a5 = sh[2*(lane+64) + 1];
            float4 a6 = sh[2*(lane+96)],       a7 = sh[2*(lane+96) + 1];
            float bestv = -3.0e38f; int bestr = 0;
            float* od = out + (size_t)d * V;
            const int base = b * 32 + warp;
            for (int r = base; r < V; r += NA * 64) {
                int r2 = r + NA * 32;
                bool ok2 = (r2 < V);
                float s0 = row_dot(r, lane, a0,a1,a2,a3,a4,a5,a6,a7);
                float s1 = ok2 ? row_dot(r2, lane, a0,a1,a2,a3,a4,a5,a6,a7) : 0.f;
                warp_red2(s0, s1);
                if (lane == 0) {
                    s0 += outb[r];
                    __stcs(od + r, s0);
                    if (s0 > bestv) { bestv = s0; bestr = r; }
                    if (ok2) {
                        s1 += outb[r2];
                        __stcs(od + r2, s1);
                        if (s1 > bestv) { bestv = s1; bestr = r2; }
                    }
                }
            }
            if (lane == 0) {
                unsigned u = __float_as_uint(bestv);
                u = (u & 0x80000000u) ? ~u : (u | 0x80000000u);
                s_key[warp] = ((unsigned long long)u << 32) |
                              (unsigned long long)(0xFFFFFFFFu - (unsigned)bestr);
            }
            __syncthreads();
            if (tid == 0) {
                unsigned long long kk = s_key[0];
                for (int w_ = 1; w_ < 32; w_++) if (s_key[w_] > kk) kk = s_key[w_];
                g_part[b] = kk;
            }
            ++epa;
            async_bar(epa, b == 0);
            if (b == 0) {
                if (warp == 0) {
                    unsigned long long kk = 0ull;
                    for (int q = lane; q < NA; q += 32) {
                        unsigned long long t2 = __ldcg((const unsigned long long*)(g_part + q));
                        if (t2 > kk) kk = t2;
                    }
                    #pragma unroll
                    for (int o = 16; o > 0; o >>= 1) {
                        unsigned long long ok = __shfl_down_sync(0xffffffffu, kk, o);
                        if (ok > kk) kk = ok;
                    }
                    if (lane == 0)
                        s_idx = (int)(0xFFFFFFFFu - (unsigned)(kk & 0xFFFFFFFFull));
                }
                __syncthreads();
                int idx = s_idx;
                float e = embeds[(size_t)idx * H + tid];
                g_xin[tid] = fmaxf(e, 0.f);                  // feedback for step d+1
                if (tid == 0 && out_seq) out_seq[d] = (float)idx;
            }
        } else {
            // ---- B (blocks 132..147): w1h -> scores(d+1) -> softmax+ctx(d+1) ----
            const int q = b - NA;                            // 0..15
            float4* sh = (float4*)s_h;
            const float4* hv = (const float4*)g_h[pout];
            for (int k = tid; k < H4; k += NT) sh[k] = __ldcg(hv + k);
            __syncthreads();
            {   // w1h: 64 rows per block, 2 per warp (interleaved reduction)
                int r0 = q * 64 + warp * 2, r1 = r0 + 1;
                const float4* w0 = (const float4*)(w1 + (size_t)r0 * H);
                const float4* w1p = (const float4*)(w1 + (size_t)r1 * H);
                float s0 = 0.f, s1 = 0.f;
                #pragma unroll 4
                for (int k = lane; k < H4; k += 32) {
                    s0 += dot4(w0[k],  sh[k]);
                    s1 += dot4(w1p[k], sh[k]);
                }
                warp_red2(s0, s1);
                if (lane == 0) { g_w1h[r0] = s0; g_w1h[r1] = s1; }
            }
            bsync_bar(++epb);
            for (int k = tid; k < H4; k += NT) sh[k] = __ldcg((const float4*)g_w1h + k);
            __syncthreads();
            {   // scores: 16 rows per block, ALL in parallel (2 warps per row, 1 sync)
                int row = warp >> 1, half = warp & 1;        // row 0..15, half 0..1
                int i = q * 16 + row;
                int jb = half * 512;
                float val = 0.f;
                #pragma unroll 4
                for (int k = 0; k < 16; k++) {
                    int j = jb + lane + k * 32;
                    val += v[j] * tanhf(s_h[j] + __ldcg(&g_Ew2[i*H + j]));
                }
                val = warp_red(val);
                if (lane == 0) s_r2[warp] = val;             // 32 partials
                __syncthreads();
                if (tid < 16)
                    g_scores[q * 16 + tid] = s_r2[2*tid] + s_r2[2*tid + 1];
            }
            bsync_bar(++epb);
            {   // softmax (redundant) + ctx: 64 elements per block, 2 per warp
                if (tid < L) s_sc[tid] = __ldcg(g_scores + tid);
                __syncthreads();
                float mval = (tid < L) ? s_sc[tid] : -3.0e38f;
                #pragma unroll
                for (int o = 16; o > 0; o >>= 1)
                    mval = fmaxf(mval, __shfl_down_sync(0xffffffffu, mval, o));
                if (lane == 0) s_red[warp] = mval;
                __syncthreads();
                if (tid == 0) {
                    float mm = s_red[0];
                    for (int w_ = 1; w_ < 32; w_++) mm = fmaxf(mm, s_red[w_]);
                    s_red[0] = mm;
                }
                __syncthreads();
                float mx = s_red[0];
                float evv = (tid < L) ? expf(s_sc[tid] - mx) : 0.f;
                __syncthreads();
                if (tid < L) s_sc[tid] = evv;
                float sv2 = warp_red(evv);
                if (lane == 0) s_red[warp] = sv2;
                __syncthreads();
                if (tid == 0) {
                    float ss = 0.f;
                    for (int w_ = 0; w_ < 32; w_++) ss += s_red[w_];
                    s_red[0] = 1.f / ss;
                }
                __syncthreads();
                float inv = s_red[0];
                int j0 = q * 64 + warp * 2;
                float acc0 = 0.f, acc1 = 0.f;
                #pragma unroll 4
                for (int i = lane; i < L; i += 32) {
                    float sc = s_sc[i];
                    acc0 += sc * __ldcg(&g_ET[j0*L + i]);
                    acc1 += sc * __ldcg(&g_ET[(j0+1)*L + i]);
                }
                warp_red2(acc0, acc1);
                if (lane == 0) {
                    g_xin[H + j0]     = acc0 * inv;
                    g_xin[H + j0 + 1] = acc1 * inv;
                }
            }
        }
        gsync(++epg);
    }
}

// ---------------- launch: 2-node graph ----------------
extern "C" void kernel_launch(void* const* d_in, const int* in_sizes, int n_in,
                              void* d_out, int out_size)
{
    const int*   seq    = (const int*)  d_in[0];
    const float* embeds = (const float*)d_in[1];
    const float* eWih = (const float*)d_in[2],  *eWhh = (const float*)d_in[3];
    const float* ebih = (const float*)d_in[4],  *ebhh = (const float*)d_in[5];
    const float* dWih = (const float*)d_in[6],  *dWhh = (const float*)d_in[7];
    const float* dbih = (const float*)d_in[8],  *dbhh = (const float*)d_in[9];
    const float* outW = (const float*)d_in[10], *outb = (const float*)d_in[11];
    const float* v    = (const float*)d_in[12];
    const float* w1   = (const float*)d_in[13], *w2   = (const float*)d_in[14];

    float* out = (float*)d_out;
    float* out_seq = (out_size >= L*V + L) ? out + (size_t)L*V : nullptr;

    prep_kernel<<<2048, 256>>>(outW, dWih, dWhh, eWih, eWhh);
    model_kernel<<<NB, NT>>>(seq, embeds, ebih, ebhh,
                             dbih, dbhh, outb, v, w1, w2, out, out_seq);
}